// round 10
// baseline (speedup 1.0000x reference)
#include <cuda_runtime.h>
#include <cuda_bf16.h>
#include <cstdint>

#define BB 2
#define SS 2048
#define EE 512
#define HH 8
#define DD 64
#define NKV ((size_t)BB * SS * HH * DD)   // 2097152

typedef unsigned long long ull;

// ---------------- bf16 helpers ----------------
// pack {lo,hi} floats -> bf16x2 word (lo in low 16 bits)
__device__ __forceinline__ uint32_t cvt2(float lo, float hi) {
    uint32_t r; asm("cvt.rn.bf16x2.f32 %0, %1, %2;" : "=r"(r) : "f"(hi), "f"(lo)); return r;
}
__device__ __forceinline__ float lof(uint32_t w) { return __uint_as_float(w << 16); }
__device__ __forceinline__ float hif(uint32_t w) { return __uint_as_float(w & 0xffff0000u); }

__device__ __forceinline__ uint32_t smem_to_u32(const void* p) {
    uint32_t a; asm("{ .reg .u64 t; cvta.to.shared.u64 t, %1; cvt.u32.u64 %0, t; }" : "=r"(a) : "l"(p)); return a;
}

// ---------------- mma.sync + ldmatrix (baseline PTX, OK on compute_103) ----
__device__ __forceinline__ void mma_bf16(float* c, const uint32_t* a, uint32_t b0, uint32_t b1) {
    asm volatile("mma.sync.aligned.m16n8k16.row.col.f32.bf16.bf16.f32 "
        "{%0,%1,%2,%3}, {%4,%5,%6,%7}, {%8,%9}, {%0,%1,%2,%3};"
        : "+f"(c[0]), "+f"(c[1]), "+f"(c[2]), "+f"(c[3])
        : "r"(a[0]), "r"(a[1]), "r"(a[2]), "r"(a[3]), "r"(b0), "r"(b1));
}
__device__ __forceinline__ void ldsm_x4(uint32_t* r, uint32_t addr) {
    asm volatile("ldmatrix.sync.aligned.m8n8.x4.shared.b16 {%0,%1,%2,%3}, [%4];"
        : "=r"(r[0]), "=r"(r[1]), "=r"(r[2]), "=r"(r[3]) : "r"(addr));
}
__device__ __forceinline__ void ldsm_x4_t(uint32_t* r, uint32_t addr) {
    asm volatile("ldmatrix.sync.aligned.m8n8.x4.trans.shared.b16 {%0,%1,%2,%3}, [%4];"
        : "=r"(r[0]), "=r"(r[1]), "=r"(r[2]), "=r"(r[3]) : "r"(addr));
}

// ---------------- scratch ----------------
__device__ float g_Q[(size_t)BB * SS * EE];
__device__ float g_AO[(size_t)BB * SS * EE];
__device__ ull g_maskBits[(size_t)BB * SS * SS / 64];
__device__ int g_maskKind;
__device__ __nv_bfloat16 g_KVsp[4][NKV];   // planes: Kh, Kl, Vh, Vl

// ---------------- mask dtype detect + bitpack ----------------
__global__ void detect_mask_kernel(const unsigned int* __restrict__ w)
{
    int i32ok = 1, f32ok = 1;
    for (int i = threadIdx.x; i < 16384; i += 256) {
        unsigned int v = w[i];
        if (v > 1u) i32ok = 0;
        if (v != 0u && v != 0x3F800000u) f32ok = 0;
    }
    i32ok = __syncthreads_and(i32ok);
    f32ok = __syncthreads_and(f32ok);
    if (threadIdx.x == 0) g_maskKind = i32ok ? 1 : (f32ok ? 2 : 0);
}

__global__ __launch_bounds__(256)
void bitpack_mask_kernel(const void* __restrict__ mask)
{
    size_t u = (size_t)blockIdx.x * 256 + threadIdx.x;
    int kind = g_maskKind;
    ull bits = 0;
    if (kind == 1) {
        const int4* p = (const int4*)mask + u * 16;
        #pragma unroll
        for (int w = 0; w < 16; ++w) {
            int4 a = p[w];
            bits |= ((ull)(a.x != 0)) << (4 * w) | ((ull)(a.y != 0)) << (4 * w + 1) |
                    ((ull)(a.z != 0)) << (4 * w + 2) | ((ull)(a.w != 0)) << (4 * w + 3);
        }
    } else if (kind == 2) {
        const float4* p = (const float4*)mask + u * 16;
        #pragma unroll
        for (int w = 0; w < 16; ++w) {
            float4 a = p[w];
            bits |= ((ull)(a.x != 0.f)) << (4 * w) | ((ull)(a.y != 0.f)) << (4 * w + 1) |
                    ((ull)(a.z != 0.f)) << (4 * w + 2) | ((ull)(a.w != 0.f)) << (4 * w + 3);
        }
    } else {
        const ull* p = (const ull*)mask + u * 8;
        #pragma unroll
        for (int w = 0; w < 8; ++w) {
            ull v = p[w];
            #pragma unroll
            for (int b8 = 0; b8 < 8; ++b8)
                bits |= ((ull)(((v >> (8 * b8)) & 0xffull) != 0)) << (8 * w + b8);
        }
    }
    g_maskBits[u] = bits;
}

// ---------------- K/V bf16 hi/lo split precompute ----------------
__global__ __launch_bounds__(256)
void kvsplit_kernel(const float* __restrict__ K, const float* __restrict__ V)
{
    size_t i4 = (size_t)blockIdx.x * 256 + threadIdx.x;   // float4 index
    {
        float4 v = ((const float4*)K)[i4];
        uint32_t h0 = cvt2(v.x, v.y), h1 = cvt2(v.z, v.w);
        ((uint2*)g_KVsp[0])[i4] = make_uint2(h0, h1);
        ((uint2*)g_KVsp[1])[i4] = make_uint2(cvt2(v.x - lof(h0), v.y - hif(h0)),
                                             cvt2(v.z - lof(h1), v.w - hif(h1)));
    }
    {
        float4 v = ((const float4*)V)[i4];
        uint32_t h0 = cvt2(v.x, v.y), h1 = cvt2(v.z, v.w);
        ((uint2*)g_KVsp[2])[i4] = make_uint2(h0, h1);
        ((uint2*)g_KVsp[3])[i4] = make_uint2(cvt2(v.x - lof(h0), v.y - hif(h0)),
                                             cvt2(v.z - lof(h1), v.w - hif(h1)));
    }
}

// ---------------- HMMA GEMM: C[M x 512] = A[M x 512] * B[512 x 512] --------
#define GLA 40
#define GLB 72

__global__ __launch_bounds__(128, 2)
void gemm_mma_kernel(const float* __restrict__ A, const float* __restrict__ Bm,
                     float* __restrict__ C)
{
    __shared__ __align__(16) __nv_bfloat16 sAh[128 * GLA], sAl[128 * GLA];
    __shared__ __align__(16) __nv_bfloat16 sBh[32 * GLB], sBl[32 * GLB];

    const int tid = threadIdx.x;
    const int warp = tid >> 5, lane = tid & 31;
    const int g = lane >> 3, lrow = lane & 7;
    const int mbase = blockIdx.x * 128, nbase = blockIdx.y * 64;

    float Ca[2][8][4];
    #pragma unroll
    for (int i = 0; i < 2; ++i)
        #pragma unroll
        for (int j = 0; j < 8; ++j)
            #pragma unroll
            for (int r = 0; r < 4; ++r) Ca[i][j][r] = 0.f;

    const int arow = warp * 32 + (g & 1) * 8 + lrow;
    const int acol = (g >> 1) * 8;
    const uint32_t bOff = (uint32_t)(((g & 1) * 8 + lrow) * GLB + (g >> 1) * 8) * 2;
    const uint32_t uBh = smem_to_u32(sBh), uBl = smem_to_u32(sBl);

    #pragma unroll 1
    for (int kk = 0; kk < 512; kk += 32) {
        __syncthreads();
        {
            const float4* ar = (const float4*)(A + (size_t)(mbase + tid) * 512 + kk);
            uint32_t* ah = (uint32_t*)(sAh + tid * GLA);
            uint32_t* al = (uint32_t*)(sAl + tid * GLA);
            #pragma unroll
            for (int i = 0; i < 8; ++i) {
                float4 v = ar[i];
                uint32_t h0 = cvt2(v.x, v.y), h1 = cvt2(v.z, v.w);
                ah[2 * i] = h0; ah[2 * i + 1] = h1;
                al[2 * i] = cvt2(v.x - lof(h0), v.y - hif(h0));
                al[2 * i + 1] = cvt2(v.z - lof(h1), v.w - hif(h1));
            }
        }
        {
            int br = tid >> 2, bc = (tid & 3) * 16;
            const float4* bp = (const float4*)(Bm + (size_t)(kk + br) * 512 + nbase + bc);
            uint32_t* bh = (uint32_t*)(sBh + br * GLB + bc);
            uint32_t* bl = (uint32_t*)(sBl + br * GLB + bc);
            #pragma unroll
            for (int i = 0; i < 4; ++i) {
                float4 v = bp[i];
                uint32_t h0 = cvt2(v.x, v.y), h1 = cvt2(v.z, v.w);
                bh[2 * i] = h0; bh[2 * i + 1] = h1;
                bl[2 * i] = cvt2(v.x - lof(h0), v.y - hif(h0));
                bl[2 * i + 1] = cvt2(v.z - lof(h1), v.w - hif(h1));
            }
        }
        __syncthreads();

        uint32_t Ah[2][2][4], Al[2][2][4];
        #pragma unroll
        for (int i = 0; i < 2; ++i)
            #pragma unroll
            for (int kb = 0; kb < 2; ++kb) {
                ldsm_x4(Ah[i][kb], smem_to_u32(sAh + (arow + i * 16) * GLA + acol + kb * 16));
                ldsm_x4(Al[i][kb], smem_to_u32(sAl + (arow + i * 16) * GLA + acol + kb * 16));
            }

        #pragma unroll
        for (int np = 0; np < 4; ++np) {
            #pragma unroll
            for (int kb = 0; kb < 2; ++kb) {
                uint32_t Bh[4], Bl[4];
                uint32_t off = (uint32_t)(kb * 16 * GLB + np * 16) * 2;
                ldsm_x4_t(Bh, uBh + off + bOff);
                ldsm_x4_t(Bl, uBl + off + bOff);
                #pragma unroll
                for (int i = 0; i < 2; ++i) mma_bf16(Ca[i][2 * np], Ah[i][kb], Bh[0], Bh[1]);
                #pragma unroll
                for (int i = 0; i < 2; ++i) mma_bf16(Ca[i][2 * np + 1], Ah[i][kb], Bh[2], Bh[3]);
                #pragma unroll
                for (int i = 0; i < 2; ++i) mma_bf16(Ca[i][2 * np], Ah[i][kb], Bl[0], Bl[1]);
                #pragma unroll
                for (int i = 0; i < 2; ++i) mma_bf16(Ca[i][2 * np + 1], Ah[i][kb], Bl[2], Bl[3]);
                #pragma unroll
                for (int i = 0; i < 2; ++i) mma_bf16(Ca[i][2 * np], Al[i][kb], Bh[0], Bh[1]);
                #pragma unroll
                for (int i = 0; i < 2; ++i) mma_bf16(Ca[i][2 * np + 1], Al[i][kb], Bh[2], Bh[3]);
            }
        }
    }

    #pragma unroll
    for (int i = 0; i < 2; ++i) {
        int r0 = mbase + warp * 32 + i * 16 + (lane >> 2);
        float* c0 = C + (size_t)r0 * 512 + nbase;
        float* c1 = c0 + (size_t)8 * 512;
        #pragma unroll
        for (int nb = 0; nb < 8; ++nb) {
            int d = nb * 8 + (lane & 3) * 2;
            *(float2*)(c0 + d) = make_float2(Ca[i][nb][0], Ca[i][nb][1]);
            *(float2*)(c1 + d) = make_float2(Ca[i][nb][2], Ca[i][nb][3]);
        }
    }
}

// ---------------- HMMA flash attention (32 rows/warp, 128 rows/CTA) --------
#define LST 72
#define TS (64 * LST)   // one tile plane in bf16 elems

__global__ __launch_bounds__(128, 2)
void attn_mma_kernel(const ull* __restrict__ mbits,
                     const float* __restrict__ Q, float* __restrict__ O)
{
    __shared__ __align__(16) __nv_bfloat16 sT[4 * TS];   // Kh | Kl | Vh | Vl
    __nv_bfloat16* const sKh = sT;
    __nv_bfloat16* const sKl = sT + TS;
    __nv_bfloat16* const sVh = sT + 2 * TS;
    __nv_bfloat16* const sVl = sT + 3 * TS;

    const int b = blockIdx.z, h = blockIdx.y;
    const int qbase = blockIdx.x * 128;
    const int tid = threadIdx.x;
    const int warp = tid >> 5, lane = tid & 31;
    const int g = lane >> 3, lrow = lane & 7;

    // ---- stage Q (scaled 1/8, hi/lo): rows 0-63 in sKh/sKl, 64-127 in sVh/sVl ----
    {
        const float4* qr = (const float4*)(Q + (size_t)(b * SS + qbase + tid) * EE + h * DD);
        uint32_t* dh = (uint32_t*)((tid < 64 ? sKh : sVh) + (tid & 63) * LST);
        uint32_t* dl = (uint32_t*)((tid < 64 ? sKl : sVl) + (tid & 63) * LST);
        #pragma unroll
        for (int i = 0; i < 16; ++i) {
            float4 v = qr[i];
            v.x *= 0.125f; v.y *= 0.125f; v.z *= 0.125f; v.w *= 0.125f;
            uint32_t h0 = cvt2(v.x, v.y), h1 = cvt2(v.z, v.w);
            dh[2 * i] = h0; dh[2 * i + 1] = h1;
            dl[2 * i] = cvt2(v.x - lof(h0), v.y - hif(h0));
            dl[2 * i + 1] = cvt2(v.z - lof(h1), v.w - hif(h1));
        }
    }
    __syncthreads();

    // ---- load persistent Q A-fragments (hi/lo) ----
    uint32_t Qh[2][4][4], Ql[2][4][4];
    {
        const __nv_bfloat16* bh = (warp < 2) ? sKh : sVh;
        const __nv_bfloat16* bl = (warp < 2) ? sKl : sVl;
        const int rowbase = (warp & 1) * 32;
        const int arow = rowbase + (g & 1) * 8 + lrow;
        const int acol = (g >> 1) * 8;
        #pragma unroll
        for (int i = 0; i < 2; ++i)
            #pragma unroll
            for (int kb = 0; kb < 4; ++kb) {
                ldsm_x4(Qh[i][kb], smem_to_u32(bh + (arow + i * 16) * LST + acol + kb * 16));
                ldsm_x4(Ql[i][kb], smem_to_u32(bl + (arow + i * 16) * LST + acol + kb * 16));
            }
    }
    __syncthreads();

    float Oa[2][8][4];
    #pragma unroll
    for (int i = 0; i < 2; ++i)
        #pragma unroll
        for (int j = 0; j < 8; ++j)
            #pragma unroll
            for (int r = 0; r < 4; ++r) Oa[i][j][r] = 0.f;
    float lsum[4] = {0.f, 0.f, 0.f, 0.f};

    const uint32_t uB = smem_to_u32(sT);
    const uint32_t uKh = uB, uKl = uB + TS * 2, uVh = uB + 2 * TS * 2, uVl = uB + 3 * TS * 2;
    const uint32_t kOff = (uint32_t)(((g >> 1) * 8 + lrow) * LST + (g & 1) * 8) * 2;
    const uint32_t vOff = (uint32_t)(((g & 1) * 8 + lrow) * LST + (g >> 1) * 8) * 2;
    const ull* mrow = mbits + (size_t)(b * SS + qbase + warp * 32) * (SS / 64);

    #pragma unroll 1
    for (int t = 0; t < SS / 64; ++t) {
        const int kt = t * 64;
        __syncthreads();
        // ---- stage K/V tiles: pure 16B copies from precomputed planes ----
        #pragma unroll
        for (int r2 = 0; r2 < 2; ++r2) {
            int idx = tid + 128 * r2;
            int tile = idx >> 6, row = idx & 63;
            const uint4* src = (const uint4*)(g_KVsp[tile] +
                ((size_t)(b * SS + kt + row) * HH + h) * DD);
            uint4* dst = (uint4*)(sT + tile * TS + row * LST);
            #pragma unroll
            for (int i = 0; i < 8; ++i) dst[i] = src[i];
        }
        __syncthreads();

        // ---- S = Q K^T (3-term split) ----
        float S[2][8][4];
        #pragma unroll
        for (int i = 0; i < 2; ++i)
            #pragma unroll
            for (int j = 0; j < 8; ++j)
                #pragma unroll
                for (int r = 0; r < 4; ++r) S[i][j][r] = 0.f;

        #pragma unroll
        for (int np = 0; np < 4; ++np) {
            #pragma unroll
            for (int kb = 0; kb < 4; ++kb) {
                uint32_t Bh[4], Bl[4];
                uint32_t off = (uint32_t)(np * 16 * LST + kb * 16) * 2;
                ldsm_x4(Bh, uKh + off + kOff);
                ldsm_x4(Bl, uKl + off + kOff);
                #pragma unroll
                for (int i = 0; i < 2; ++i) mma_bf16(S[i][2 * np], Qh[i][kb], Bh[0], Bh[1]);
                #pragma unroll
                for (int i = 0; i < 2; ++i) mma_bf16(S[i][2 * np + 1], Qh[i][kb], Bh[2], Bh[3]);
                #pragma unroll
                for (int i = 0; i < 2; ++i) mma_bf16(S[i][2 * np], Qh[i][kb], Bl[0], Bl[1]);
                #pragma unroll
                for (int i = 0; i < 2; ++i) mma_bf16(S[i][2 * np + 1], Qh[i][kb], Bl[2], Bl[3]);
                #pragma unroll
                for (int i = 0; i < 2; ++i) mma_bf16(S[i][2 * np], Ql[i][kb], Bh[0], Bh[1]);
                #pragma unroll
                for (int i = 0; i < 2; ++i) mma_bf16(S[i][2 * np + 1], Ql[i][kb], Bh[2], Bh[3]);
            }
        }

        // ---- softmax (masked -> 0) + pack P A-frags hi/lo ----
        uint32_t Ph[2][4][4], Pl[2][4][4];
        #pragma unroll
        for (int i = 0; i < 2; ++i) {
            ull mw0 = mrow[(size_t)(i * 16 + (lane >> 2)) * (SS / 64) + t];
            ull mw1 = mrow[(size_t)(i * 16 + 8 + (lane >> 2)) * (SS / 64) + t];
            #pragma unroll
            for (int nb = 0; nb < 8; ++nb) {
                int p0 = nb * 8 + (lane & 3) * 2;
                float e0 = ((mw0 >> p0) & 1ull) ? 0.f : __expf(S[i][nb][0]);
                float e1 = ((mw0 >> (p0 + 1)) & 1ull) ? 0.f : __expf(S[i][nb][1]);
                float e2 = ((mw1 >> p0) & 1ull) ? 0.f : __expf(S[i][nb][2]);
                float e3 = ((mw1 >> (p0 + 1)) & 1ull) ? 0.f : __expf(S[i][nb][3]);
                lsum[i * 2] += e0 + e1;
                lsum[i * 2 + 1] += e2 + e3;
                int kb = nb >> 1, sub = (nb & 1) * 2;
                uint32_t h01 = cvt2(e0, e1), h23 = cvt2(e2, e3);
                Ph[i][kb][sub] = h01;
                Ph[i][kb][sub + 1] = h23;
                Pl[i][kb][sub] = cvt2(e0 - lof(h01), e1 - hif(h01));
                Pl[i][kb][sub + 1] = cvt2(e2 - lof(h23), e3 - hif(h23));
            }
        }

        // ---- O += P V (3-term split), V frags via ldmatrix.trans ----
        #pragma unroll
        for (int dp = 0; dp < 4; ++dp) {
            #pragma unroll
            for (int kb = 0; kb < 4; ++kb) {
                uint32_t Bh[4], Bl[4];
                uint32_t off = (uint32_t)(kb * 16 * LST + dp * 16) * 2;
                ldsm_x4_t(Bh, uVh + off + vOff);
                ldsm_x4_t(Bl, uVl + off + vOff);
                #pragma unroll
                for (int i = 0; i < 2; ++i) mma_bf16(Oa[i][2 * dp], Ph[i][kb], Bh[0], Bh[1]);
                #pragma unroll
                for (int i = 0; i < 2; ++i) mma_bf16(Oa[i][2 * dp + 1], Ph[i][kb], Bh[2], Bh[3]);
                #pragma unroll
                for (int i = 0; i < 2; ++i) mma_bf16(Oa[i][2 * dp], Ph[i][kb], Bl[0], Bl[1]);
                #pragma unroll
                for (int i = 0; i < 2; ++i) mma_bf16(Oa[i][2 * dp + 1], Ph[i][kb], Bl[2], Bl[3]);
                #pragma unroll
                for (int i = 0; i < 2; ++i) mma_bf16(Oa[i][2 * dp], Pl[i][kb], Bh[0], Bh[1]);
                #pragma unroll
                for (int i = 0; i < 2; ++i) mma_bf16(Oa[i][2 * dp + 1], Pl[i][kb], Bh[2], Bh[3]);
            }
        }
    }

    // ---- normalize + store ----
    #pragma unroll
    for (int i = 0; i < 4; ++i) {
        lsum[i] += __shfl_xor_sync(0xffffffffu, lsum[i], 1);
        lsum[i] += __shfl_xor_sync(0xffffffffu, lsum[i], 2);
    }
    #pragma unroll
    for (int i = 0; i < 2; ++i) {
        float inv0 = 1.f / lsum[i * 2];
        float inv1 = 1.f / lsum[i * 2 + 1];
        int r0 = qbase + warp * 32 + i * 16 + (lane >> 2);
        float* o0 = O + (size_t)(b * SS + r0) * EE + h * DD;
        float* o1 = o0 + (size_t)8 * EE;
        #pragma unroll
        for (int nb = 0; nb < 8; ++nb) {
            int d = nb * 8 + (lane & 3) * 2;
            *(float2*)(o0 + d) = make_float2(Oa[i][nb][0] * inv0, Oa[i][nb][1] * inv0);
            *(float2*)(o1 + d) = make_float2(Oa[i][nb][2] * inv1, Oa[i][nb][3] * inv1);
        }
    }
}

// ---------------- launch ----------------
extern "C" void kernel_launch(void* const* d_in, const int* in_sizes, int n_in,
                              void* d_out, int out_size)
{
    const float* inputs = (const float*)d_in[0];
    const float* keys = (const float*)d_in[1];
    const float* values = (const float*)d_in[2];
    const float* wq = (const float*)d_in[3];
    const float* wo = (const float*)d_in[4];
    const void* mask_raw = d_in[5];
    float* out = (float*)d_out;

    float* qbuf; float* aobuf; ull* mbits;
    cudaGetSymbolAddress((void**)&qbuf, g_Q);
    cudaGetSymbolAddress((void**)&aobuf, g_AO);
    cudaGetSymbolAddress((void**)&mbits, g_maskBits);

    detect_mask_kernel<<<1, 256>>>((const unsigned int*)mask_raw);
    bitpack_mask_kernel<<<(BB * SS * SS / 64) / 256, 256>>>(mask_raw);
    kvsplit_kernel<<<(int)(NKV / 4 / 256), 256>>>(keys, values);

    dim3 ggrid(32, 8);
    gemm_mma_kernel<<<ggrid, 128>>>(inputs, wq, qbuf);
    attn_mma_kernel<<<dim3(SS / 128, HH, BB), 128>>>(mbits, qbuf, aobuf);
    gemm_mma_kernel<<<ggrid, 128>>>(aobuf, wo, out);
}

// round 11
// speedup vs baseline: 1.5528x; 1.5528x over previous
#include <cuda_runtime.h>
#include <cuda_bf16.h>
#include <cuda_fp16.h>
#include <cstdint>

#define BB 2
#define SS 2048
#define EE 512
#define HH 8
#define DD 64
#define NKV ((size_t)BB * SS * HH * DD)   // 2097152

typedef unsigned long long ull;

// ---------------- bf16 helpers (GEMM path) ----------------
__device__ __forceinline__ uint32_t cvt2(float lo, float hi) {
    uint32_t r; asm("cvt.rn.bf16x2.f32 %0, %1, %2;" : "=r"(r) : "f"(hi), "f"(lo)); return r;
}
__device__ __forceinline__ float lof(uint32_t w) { return __uint_as_float(w << 16); }
__device__ __forceinline__ float hif(uint32_t w) { return __uint_as_float(w & 0xffff0000u); }

// ---------------- fp16 helpers (attention path) ----------------
__device__ __forceinline__ uint32_t h2bits(__half2 h) {
    uint32_t u; *(__half2*)&u = h; return u;
}
__device__ __forceinline__ uint32_t packh2(float lo, float hi) {
    return h2bits(__floats2half2_rn(lo, hi));
}

__device__ __forceinline__ uint32_t smem_to_u32(const void* p) {
    uint32_t a; asm("{ .reg .u64 t; cvta.to.shared.u64 t, %1; cvt.u32.u64 %0, t; }" : "=r"(a) : "l"(p)); return a;
}

// ---------------- mma.sync + ldmatrix (baseline PTX, OK on compute_103) ----
__device__ __forceinline__ void mma_bf16(float* c, const uint32_t* a, uint32_t b0, uint32_t b1) {
    asm volatile("mma.sync.aligned.m16n8k16.row.col.f32.bf16.bf16.f32 "
        "{%0,%1,%2,%3}, {%4,%5,%6,%7}, {%8,%9}, {%0,%1,%2,%3};"
        : "+f"(c[0]), "+f"(c[1]), "+f"(c[2]), "+f"(c[3])
        : "r"(a[0]), "r"(a[1]), "r"(a[2]), "r"(a[3]), "r"(b0), "r"(b1));
}
__device__ __forceinline__ void mma_f16(float* c, const uint32_t* a, uint32_t b0, uint32_t b1) {
    asm volatile("mma.sync.aligned.m16n8k16.row.col.f32.f16.f16.f32 "
        "{%0,%1,%2,%3}, {%4,%5,%6,%7}, {%8,%9}, {%0,%1,%2,%3};"
        : "+f"(c[0]), "+f"(c[1]), "+f"(c[2]), "+f"(c[3])
        : "r"(a[0]), "r"(a[1]), "r"(a[2]), "r"(a[3]), "r"(b0), "r"(b1));
}
__device__ __forceinline__ void ldsm_x4(uint32_t* r, uint32_t addr) {
    asm volatile("ldmatrix.sync.aligned.m8n8.x4.shared.b16 {%0,%1,%2,%3}, [%4];"
        : "=r"(r[0]), "=r"(r[1]), "=r"(r[2]), "=r"(r[3]) : "r"(addr));
}
__device__ __forceinline__ void ldsm_x4_t(uint32_t* r, uint32_t addr) {
    asm volatile("ldmatrix.sync.aligned.m8n8.x4.trans.shared.b16 {%0,%1,%2,%3}, [%4];"
        : "=r"(r[0]), "=r"(r[1]), "=r"(r[2]), "=r"(r[3]) : "r"(addr));
}

// ---------------- scratch ----------------
__device__ float g_Q[(size_t)BB * SS * EE];
__device__ float g_AO[(size_t)BB * SS * EE];
__device__ ull g_maskBits[(size_t)BB * SS * SS / 64];
__device__ int g_maskKind;
__device__ __half g_KVsp[4][NKV];   // fp16 planes: Kh, Kl, Vh, Vl

// ---------------- mask dtype detect + bitpack ----------------
__global__ void detect_mask_kernel(const unsigned int* __restrict__ w)
{
    int i32ok = 1, f32ok = 1;
    for (int i = threadIdx.x; i < 16384; i += 256) {
        unsigned int v = w[i];
        if (v > 1u) i32ok = 0;
        if (v != 0u && v != 0x3F800000u) f32ok = 0;
    }
    i32ok = __syncthreads_and(i32ok);
    f32ok = __syncthreads_and(f32ok);
    if (threadIdx.x == 0) g_maskKind = i32ok ? 1 : (f32ok ? 2 : 0);
}

__global__ __launch_bounds__(256)
void bitpack_mask_kernel(const void* __restrict__ mask)
{
    size_t u = (size_t)blockIdx.x * 256 + threadIdx.x;
    int kind = g_maskKind;
    ull bits = 0;
    if (kind == 1) {
        const int4* p = (const int4*)mask + u * 16;
        #pragma unroll
        for (int w = 0; w < 16; ++w) {
            int4 a = p[w];
            bits |= ((ull)(a.x != 0)) << (4 * w) | ((ull)(a.y != 0)) << (4 * w + 1) |
                    ((ull)(a.z != 0)) << (4 * w + 2) | ((ull)(a.w != 0)) << (4 * w + 3);
        }
    } else if (kind == 2) {
        const float4* p = (const float4*)mask + u * 16;
        #pragma unroll
        for (int w = 0; w < 16; ++w) {
            float4 a = p[w];
            bits |= ((ull)(a.x != 0.f)) << (4 * w) | ((ull)(a.y != 0.f)) << (4 * w + 1) |
                    ((ull)(a.z != 0.f)) << (4 * w + 2) | ((ull)(a.w != 0.f)) << (4 * w + 3);
        }
    } else {
        const ull* p = (const ull*)mask + u * 8;
        #pragma unroll
        for (int w = 0; w < 8; ++w) {
            ull v = p[w];
            #pragma unroll
            for (int b8 = 0; b8 < 8; ++b8)
                bits |= ((ull)(((v >> (8 * b8)) & 0xffull) != 0)) << (8 * w + b8);
        }
    }
    g_maskBits[u] = bits;
}

// ---------------- K/V fp16 hi/lo split precompute ----------------
__global__ __launch_bounds__(256)
void kvsplit_kernel(const float* __restrict__ K, const float* __restrict__ V)
{
    size_t i4 = (size_t)blockIdx.x * 256 + threadIdx.x;   // float4 index
    {
        float4 v = ((const float4*)K)[i4];
        __half2 h01 = __floats2half2_rn(v.x, v.y);
        __half2 h23 = __floats2half2_rn(v.z, v.w);
        ((uint2*)g_KVsp[0])[i4] = make_uint2(h2bits(h01), h2bits(h23));
        ((uint2*)g_KVsp[1])[i4] = make_uint2(
            packh2(v.x - __low2float(h01), v.y - __high2float(h01)),
            packh2(v.z - __low2float(h23), v.w - __high2float(h23)));
    }
    {
        float4 v = ((const float4*)V)[i4];
        __half2 h01 = __floats2half2_rn(v.x, v.y);
        __half2 h23 = __floats2half2_rn(v.z, v.w);
        ((uint2*)g_KVsp[2])[i4] = make_uint2(h2bits(h01), h2bits(h23));
        ((uint2*)g_KVsp[3])[i4] = make_uint2(
            packh2(v.x - __low2float(h01), v.y - __high2float(h01)),
            packh2(v.z - __low2float(h23), v.w - __high2float(h23)));
    }
}

// ---------------- HMMA GEMM: C[M x 512] = A[M x 512] * B[512 x 512] --------
#define GLA 40
#define GLB 72

__global__ __launch_bounds__(128, 2)
void gemm_mma_kernel(const float* __restrict__ A, const float* __restrict__ Bm,
                     float* __restrict__ C)
{
    __shared__ __align__(16) __nv_bfloat16 sAh[128 * GLA], sAl[128 * GLA];
    __shared__ __align__(16) __nv_bfloat16 sBh[32 * GLB], sBl[32 * GLB];

    const int tid = threadIdx.x;
    const int warp = tid >> 5, lane = tid & 31;
    const int g = lane >> 3, lrow = lane & 7;
    const int mbase = blockIdx.x * 128, nbase = blockIdx.y * 64;

    float Ca[2][8][4];
    #pragma unroll
    for (int i = 0; i < 2; ++i)
        #pragma unroll
        for (int j = 0; j < 8; ++j)
            #pragma unroll
            for (int r = 0; r < 4; ++r) Ca[i][j][r] = 0.f;

    const int arow = warp * 32 + (g & 1) * 8 + lrow;
    const int acol = (g >> 1) * 8;
    const uint32_t bOff = (uint32_t)(((g & 1) * 8 + lrow) * GLB + (g >> 1) * 8) * 2;
    const uint32_t uBh = smem_to_u32(sBh), uBl = smem_to_u32(sBl);

    #pragma unroll 1
    for (int kk = 0; kk < 512; kk += 32) {
        __syncthreads();
        {
            const float4* ar = (const float4*)(A + (size_t)(mbase + tid) * 512 + kk);
            uint32_t* ah = (uint32_t*)(sAh + tid * GLA);
            uint32_t* al = (uint32_t*)(sAl + tid * GLA);
            #pragma unroll
            for (int i = 0; i < 8; ++i) {
                float4 v = ar[i];
                uint32_t h0 = cvt2(v.x, v.y), h1 = cvt2(v.z, v.w);
                ah[2 * i] = h0; ah[2 * i + 1] = h1;
                al[2 * i] = cvt2(v.x - lof(h0), v.y - hif(h0));
                al[2 * i + 1] = cvt2(v.z - lof(h1), v.w - hif(h1));
            }
        }
        {
            int br = tid >> 2, bc = (tid & 3) * 16;
            const float4* bp = (const float4*)(Bm + (size_t)(kk + br) * 512 + nbase + bc);
            uint32_t* bh = (uint32_t*)(sBh + br * GLB + bc);
            uint32_t* bl = (uint32_t*)(sBl + br * GLB + bc);
            #pragma unroll
            for (int i = 0; i < 4; ++i) {
                float4 v = bp[i];
                uint32_t h0 = cvt2(v.x, v.y), h1 = cvt2(v.z, v.w);
                bh[2 * i] = h0; bh[2 * i + 1] = h1;
                bl[2 * i] = cvt2(v.x - lof(h0), v.y - hif(h0));
                bl[2 * i + 1] = cvt2(v.z - lof(h1), v.w - hif(h1));
            }
        }
        __syncthreads();

        uint32_t Ah[2][2][4], Al[2][2][4];
        #pragma unroll
        for (int i = 0; i < 2; ++i)
            #pragma unroll
            for (int kb = 0; kb < 2; ++kb) {
                ldsm_x4(Ah[i][kb], smem_to_u32(sAh + (arow + i * 16) * GLA + acol + kb * 16));
                ldsm_x4(Al[i][kb], smem_to_u32(sAl + (arow + i * 16) * GLA + acol + kb * 16));
            }

        #pragma unroll
        for (int np = 0; np < 4; ++np) {
            #pragma unroll
            for (int kb = 0; kb < 2; ++kb) {
                uint32_t Bh[4], Bl[4];
                uint32_t off = (uint32_t)(kb * 16 * GLB + np * 16) * 2;
                ldsm_x4_t(Bh, uBh + off + bOff);
                ldsm_x4_t(Bl, uBl + off + bOff);
                #pragma unroll
                for (int i = 0; i < 2; ++i) mma_bf16(Ca[i][2 * np], Ah[i][kb], Bh[0], Bh[1]);
                #pragma unroll
                for (int i = 0; i < 2; ++i) mma_bf16(Ca[i][2 * np + 1], Ah[i][kb], Bh[2], Bh[3]);
                #pragma unroll
                for (int i = 0; i < 2; ++i) mma_bf16(Ca[i][2 * np], Ah[i][kb], Bl[0], Bl[1]);
                #pragma unroll
                for (int i = 0; i < 2; ++i) mma_bf16(Ca[i][2 * np + 1], Ah[i][kb], Bl[2], Bl[3]);
                #pragma unroll
                for (int i = 0; i < 2; ++i) mma_bf16(Ca[i][2 * np], Al[i][kb], Bh[0], Bh[1]);
                #pragma unroll
                for (int i = 0; i < 2; ++i) mma_bf16(Ca[i][2 * np + 1], Al[i][kb], Bh[2], Bh[3]);
            }
        }
    }

    #pragma unroll
    for (int i = 0; i < 2; ++i) {
        int r0 = mbase + warp * 32 + i * 16 + (lane >> 2);
        float* c0 = C + (size_t)r0 * 512 + nbase;
        float* c1 = c0 + (size_t)8 * 512;
        #pragma unroll
        for (int nb = 0; nb < 8; ++nb) {
            int d = nb * 8 + (lane & 3) * 2;
            *(float2*)(c0 + d) = make_float2(Ca[i][nb][0], Ca[i][nb][1]);
            *(float2*)(c1 + d) = make_float2(Ca[i][nb][2], Ca[i][nb][3]);
        }
    }
}

// ---------------- HMMA flash attention (fp16; P single-term) ---------------
#define LST 72
#define TS (64 * LST)   // one tile plane in fp16 elems

__global__ __launch_bounds__(128, 2)
void attn_mma_kernel(const ull* __restrict__ mbits,
                     const float* __restrict__ Q, float* __restrict__ O)
{
    __shared__ __align__(16) __half sT[4 * TS];   // Kh | Kl | Vh | Vl
    __half* const sKh = sT;
    __half* const sKl = sT + TS;
    __half* const sVh = sT + 2 * TS;
    __half* const sVl = sT + 3 * TS;

    const int b = blockIdx.z, h = blockIdx.y;
    const int qbase = blockIdx.x * 128;
    const int tid = threadIdx.x;
    const int warp = tid >> 5, lane = tid & 31;
    const int g = lane >> 3, lrow = lane & 7;

    // ---- stage Q (scaled 1/8, fp16 hi/lo): rows 0-63 in sKh/sKl, 64-127 in sVh/sVl ----
    {
        const float4* qr = (const float4*)(Q + (size_t)(b * SS + qbase + tid) * EE + h * DD);
        uint32_t* dh = (uint32_t*)((tid < 64 ? sKh : sVh) + (tid & 63) * LST);
        uint32_t* dl = (uint32_t*)((tid < 64 ? sKl : sVl) + (tid & 63) * LST);
        #pragma unroll
        for (int i = 0; i < 16; ++i) {
            float4 v = qr[i];
            v.x *= 0.125f; v.y *= 0.125f; v.z *= 0.125f; v.w *= 0.125f;
            __half2 h01 = __floats2half2_rn(v.x, v.y);
            __half2 h23 = __floats2half2_rn(v.z, v.w);
            dh[2 * i] = h2bits(h01); dh[2 * i + 1] = h2bits(h23);
            dl[2 * i] = packh2(v.x - __low2float(h01), v.y - __high2float(h01));
            dl[2 * i + 1] = packh2(v.z - __low2float(h23), v.w - __high2float(h23));
        }
    }
    __syncthreads();

    // ---- load persistent Q A-fragments (hi/lo) ----
    uint32_t Qh[2][4][4], Ql[2][4][4];
    {
        const __half* bh = (warp < 2) ? sKh : sVh;
        const __half* bl = (warp < 2) ? sKl : sVl;
        const int rowbase = (warp & 1) * 32;
        const int arow = rowbase + (g & 1) * 8 + lrow;
        const int acol = (g >> 1) * 8;
        #pragma unroll
        for (int i = 0; i < 2; ++i)
            #pragma unroll
            for (int kb = 0; kb < 4; ++kb) {
                ldsm_x4(Qh[i][kb], smem_to_u32(bh + (arow + i * 16) * LST + acol + kb * 16));
                ldsm_x4(Ql[i][kb], smem_to_u32(bl + (arow + i * 16) * LST + acol + kb * 16));
            }
    }
    __syncthreads();

    float Oa[2][8][4];
    #pragma unroll
    for (int i = 0; i < 2; ++i)
        #pragma unroll
        for (int j = 0; j < 8; ++j)
            #pragma unroll
            for (int r = 0; r < 4; ++r) Oa[i][j][r] = 0.f;
    float lsum[4] = {0.f, 0.f, 0.f, 0.f};

    const uint32_t uB = smem_to_u32(sT);
    const uint32_t uKh = uB, uKl = uB + TS * 2, uVh = uB + 2 * TS * 2, uVl = uB + 3 * TS * 2;
    const uint32_t kOff = (uint32_t)(((g >> 1) * 8 + lrow) * LST + (g & 1) * 8) * 2;
    const uint32_t vOff = (uint32_t)(((g & 1) * 8 + lrow) * LST + (g >> 1) * 8) * 2;
    const ull* mrow = mbits + (size_t)(b * SS + qbase + warp * 32) * (SS / 64);

    #pragma unroll 1
    for (int t = 0; t < SS / 64; ++t) {
        const int kt = t * 64;
        __syncthreads();
        // ---- stage K/V tiles: pure 16B copies from precomputed fp16 planes ----
        #pragma unroll
        for (int r2 = 0; r2 < 2; ++r2) {
            int idx = tid + 128 * r2;
            int tile = idx >> 6, row = idx & 63;
            const uint4* src = (const uint4*)(g_KVsp[tile] +
                ((size_t)(b * SS + kt + row) * HH + h) * DD);
            uint4* dst = (uint4*)(sT + tile * TS + row * LST);
            #pragma unroll
            for (int i = 0; i < 8; ++i) dst[i] = src[i];
        }
        __syncthreads();

        // ---- S = Q K^T (fp16, 3-term split: Qh*Kh + Qh*Kl + Ql*Kh) ----
        float S[2][8][4];
        #pragma unroll
        for (int i = 0; i < 2; ++i)
            #pragma unroll
            for (int j = 0; j < 8; ++j)
                #pragma unroll
                for (int r = 0; r < 4; ++r) S[i][j][r] = 0.f;

        #pragma unroll
        for (int np = 0; np < 4; ++np) {
            #pragma unroll
            for (int kb = 0; kb < 4; ++kb) {
                uint32_t Bh[4], Bl[4];
                uint32_t off = (uint32_t)(np * 16 * LST + kb * 16) * 2;
                ldsm_x4(Bh, uKh + off + kOff);
                ldsm_x4(Bl, uKl + off + kOff);
                #pragma unroll
                for (int i = 0; i < 2; ++i) mma_f16(S[i][2 * np], Qh[i][kb], Bh[0], Bh[1]);
                #pragma unroll
                for (int i = 0; i < 2; ++i) mma_f16(S[i][2 * np + 1], Qh[i][kb], Bh[2], Bh[3]);
                #pragma unroll
                for (int i = 0; i < 2; ++i) mma_f16(S[i][2 * np], Qh[i][kb], Bl[0], Bl[1]);
                #pragma unroll
                for (int i = 0; i < 2; ++i) mma_f16(S[i][2 * np + 1], Qh[i][kb], Bl[2], Bl[3]);
                #pragma unroll
                for (int i = 0; i < 2; ++i) mma_f16(S[i][2 * np], Ql[i][kb], Bh[0], Bh[1]);
                #pragma unroll
                for (int i = 0; i < 2; ++i) mma_f16(S[i][2 * np + 1], Ql[i][kb], Bh[2], Bh[3]);
            }
        }

        // ---- softmax (masked -> 0) + pack P as single-term fp16 ----
        uint32_t Ph[2][4][4];
        #pragma unroll
        for (int i = 0; i < 2; ++i) {
            ull mw0 = mrow[(size_t)(i * 16 + (lane >> 2)) * (SS / 64) + t];
            ull mw1 = mrow[(size_t)(i * 16 + 8 + (lane >> 2)) * (SS / 64) + t];
            #pragma unroll
            for (int nb = 0; nb < 8; ++nb) {
                int p0 = nb * 8 + (lane & 3) * 2;
                float e0 = ((mw0 >> p0) & 1ull) ? 0.f : __expf(S[i][nb][0]);
                float e1 = ((mw0 >> (p0 + 1)) & 1ull) ? 0.f : __expf(S[i][nb][1]);
                float e2 = ((mw1 >> p0) & 1ull) ? 0.f : __expf(S[i][nb][2]);
                float e3 = ((mw1 >> (p0 + 1)) & 1ull) ? 0.f : __expf(S[i][nb][3]);
                lsum[i * 2] += e0 + e1;
                lsum[i * 2 + 1] += e2 + e3;
                int kb = nb >> 1, sub = (nb & 1) * 2;
                Ph[i][kb][sub] = packh2(e0, e1);
                Ph[i][kb][sub + 1] = packh2(e2, e3);
            }
        }

        // ---- O += P V  (P single-term; V hi/lo 2-term) ----
        #pragma unroll
        for (int dp = 0; dp < 4; ++dp) {
            #pragma unroll
            for (int kb = 0; kb < 4; ++kb) {
                uint32_t Bh[4], Bl[4];
                uint32_t off = (uint32_t)(kb * 16 * LST + dp * 16) * 2;
                ldsm_x4_t(Bh, uVh + off + vOff);
                ldsm_x4_t(Bl, uVl + off + vOff);
                #pragma unroll
                for (int i = 0; i < 2; ++i) mma_f16(Oa[i][2 * dp], Ph[i][kb], Bh[0], Bh[1]);
                #pragma unroll
                for (int i = 0; i < 2; ++i) mma_f16(Oa[i][2 * dp + 1], Ph[i][kb], Bh[2], Bh[3]);
                #pragma unroll
                for (int i = 0; i < 2; ++i) mma_f16(Oa[i][2 * dp], Ph[i][kb], Bl[0], Bl[1]);
                #pragma unroll
                for (int i = 0; i < 2; ++i) mma_f16(Oa[i][2 * dp + 1], Ph[i][kb], Bl[2], Bl[3]);
            }
        }
    }

    // ---- normalize + store ----
    #pragma unroll
    for (int i = 0; i < 4; ++i) {
        lsum[i] += __shfl_xor_sync(0xffffffffu, lsum[i], 1);
        lsum[i] += __shfl_xor_sync(0xffffffffu, lsum[i], 2);
    }
    #pragma unroll
    for (int i = 0; i < 2; ++i) {
        float inv0 = 1.f / lsum[i * 2];
        float inv1 = 1.f / lsum[i * 2 + 1];
        int r0 = qbase + warp * 32 + i * 16 + (lane >> 2);
        float* o0 = O + (size_t)(b * SS + r0) * EE + h * DD;
        float* o1 = o0 + (size_t)8 * EE;
        #pragma unroll
        for (int nb = 0; nb < 8; ++nb) {
            int d = nb * 8 + (lane & 3) * 2;
            *(float2*)(o0 + d) = make_float2(Oa[i][nb][0] * inv0, Oa[i][nb][1] * inv0);
            *(float2*)(o1 + d) = make_float2(Oa[i][nb][2] * inv1, Oa[i][nb][3] * inv1);
        }
    }
}

// ---------------- launch ----------------
extern "C" void kernel_launch(void* const* d_in, const int* in_sizes, int n_in,
                              void* d_out, int out_size)
{
    const float* inputs = (const float*)d_in[0];
    const float* keys = (const float*)d_in[1];
    const float* values = (const float*)d_in[2];
    const float* wq = (const float*)d_in[3];
    const float* wo = (const float*)d_in[4];
    const void* mask_raw = d_in[5];
    float* out = (float*)d_out;

    float* qbuf; float* aobuf; ull* mbits;
    cudaGetSymbolAddress((void**)&qbuf, g_Q);
    cudaGetSymbolAddress((void**)&aobuf, g_AO);
    cudaGetSymbolAddress((void**)&mbits, g_maskBits);

    detect_mask_kernel<<<1, 256>>>((const unsigned int*)mask_raw);
    bitpack_mask_kernel<<<(BB * SS * SS / 64) / 256, 256>>>(mask_raw);
    kvsplit_kernel<<<(int)(NKV / 4 / 256), 256>>>(keys, values);

    dim3 ggrid(32, 8);
    gemm_mma_kernel<<<ggrid, 128>>>(inputs, wq, qbuf);
    attn_mma_kernel<<<dim3(SS / 128, HH, BB), 128>>>(mbits, qbuf, aobuf);
    gemm_mma_kernel<<<ggrid, 128>>>(aobuf, wo, out);
}

// round 12
// speedup vs baseline: 2.2105x; 1.4236x over previous
#include <cuda_runtime.h>
#include <cuda_bf16.h>
#include <cuda_fp16.h>
#include <cstdint>

#define BB 2
#define SS 2048
#define EE 512
#define HH 8
#define DD 64
#define NKV ((size_t)BB * SS * HH * DD)   // 2097152

typedef unsigned long long ull;

// ---------------- bf16 helpers (GEMM path) ----------------
__device__ __forceinline__ uint32_t cvt2(float lo, float hi) {
    uint32_t r; asm("cvt.rn.bf16x2.f32 %0, %1, %2;" : "=r"(r) : "f"(hi), "f"(lo)); return r;
}
__device__ __forceinline__ float lof(uint32_t w) { return __uint_as_float(w << 16); }
__device__ __forceinline__ float hif(uint32_t w) { return __uint_as_float(w & 0xffff0000u); }

// ---------------- fp16 helpers (attention path) ----------------
__device__ __forceinline__ uint32_t h2bits(__half2 h) {
    uint32_t u; *(__half2*)&u = h; return u;
}
__device__ __forceinline__ uint32_t packh2(float lo, float hi) {
    return h2bits(__floats2half2_rn(lo, hi));
}

__device__ __forceinline__ uint32_t smem_to_u32(const void* p) {
    uint32_t a; asm("{ .reg .u64 t; cvta.to.shared.u64 t, %1; cvt.u32.u64 %0, t; }" : "=r"(a) : "l"(p)); return a;
}

// ---------------- mma.sync + ldmatrix + cp.async (baseline PTX) ----------
__device__ __forceinline__ void mma_bf16(float* c, const uint32_t* a, uint32_t b0, uint32_t b1) {
    asm volatile("mma.sync.aligned.m16n8k16.row.col.f32.bf16.bf16.f32 "
        "{%0,%1,%2,%3}, {%4,%5,%6,%7}, {%8,%9}, {%0,%1,%2,%3};"
        : "+f"(c[0]), "+f"(c[1]), "+f"(c[2]), "+f"(c[3])
        : "r"(a[0]), "r"(a[1]), "r"(a[2]), "r"(a[3]), "r"(b0), "r"(b1));
}
__device__ __forceinline__ void mma_f16(float* c, const uint32_t* a, uint32_t b0, uint32_t b1) {
    asm volatile("mma.sync.aligned.m16n8k16.row.col.f32.f16.f16.f32 "
        "{%0,%1,%2,%3}, {%4,%5,%6,%7}, {%8,%9}, {%0,%1,%2,%3};"
        : "+f"(c[0]), "+f"(c[1]), "+f"(c[2]), "+f"(c[3])
        : "r"(a[0]), "r"(a[1]), "r"(a[2]), "r"(a[3]), "r"(b0), "r"(b1));
}
__device__ __forceinline__ void ldsm_x4(uint32_t* r, uint32_t addr) {
    asm volatile("ldmatrix.sync.aligned.m8n8.x4.shared.b16 {%0,%1,%2,%3}, [%4];"
        : "=r"(r[0]), "=r"(r[1]), "=r"(r[2]), "=r"(r[3]) : "r"(addr));
}
__device__ __forceinline__ void ldsm_x4_t(uint32_t* r, uint32_t addr) {
    asm volatile("ldmatrix.sync.aligned.m8n8.x4.trans.shared.b16 {%0,%1,%2,%3}, [%4];"
        : "=r"(r[0]), "=r"(r[1]), "=r"(r[2]), "=r"(r[3]) : "r"(addr));
}
__device__ __forceinline__ void cp_async16(uint32_t dst, const void* src) {
    asm volatile("cp.async.ca.shared.global [%0], [%1], 16;" :: "r"(dst), "l"(src) : "memory");
}
#define CP_COMMIT() asm volatile("cp.async.commit_group;" ::: "memory")
#define CP_WAIT0()  asm volatile("cp.async.wait_group 0;" ::: "memory")

// ---------------- scratch ----------------
__device__ float g_Q[(size_t)BB * SS * EE];
__device__ float g_AO[(size_t)BB * SS * EE];
__device__ ull g_maskBits[(size_t)BB * SS * SS / 64];
__device__ int g_maskKind;
__device__ __half g_KVsp[3][NKV];   // fp16 planes: K, Vh, Vl

// ---------------- mask dtype detect + bitpack ----------------
__global__ void detect_mask_kernel(const unsigned int* __restrict__ w)
{
    int i32ok = 1, f32ok = 1;
    for (int i = threadIdx.x; i < 16384; i += 256) {
        unsigned int v = w[i];
        if (v > 1u) i32ok = 0;
        if (v != 0u && v != 0x3F800000u) f32ok = 0;
    }
    i32ok = __syncthreads_and(i32ok);
    f32ok = __syncthreads_and(f32ok);
    if (threadIdx.x == 0) g_maskKind = i32ok ? 1 : (f32ok ? 2 : 0);
}

__global__ __launch_bounds__(256)
void bitpack_mask_kernel(const void* __restrict__ mask)
{
    size_t u = (size_t)blockIdx.x * 256 + threadIdx.x;
    int kind = g_maskKind;
    ull bits = 0;
    if (kind == 1) {
        const int4* p = (const int4*)mask + u * 16;
        #pragma unroll
        for (int w = 0; w < 16; ++w) {
            int4 a = p[w];
            bits |= ((ull)(a.x != 0)) << (4 * w) | ((ull)(a.y != 0)) << (4 * w + 1) |
                    ((ull)(a.z != 0)) << (4 * w + 2) | ((ull)(a.w != 0)) << (4 * w + 3);
        }
    } else if (kind == 2) {
        const float4* p = (const float4*)mask + u * 16;
        #pragma unroll
        for (int w = 0; w < 16; ++w) {
            float4 a = p[w];
            bits |= ((ull)(a.x != 0.f)) << (4 * w) | ((ull)(a.y != 0.f)) << (4 * w + 1) |
                    ((ull)(a.z != 0.f)) << (4 * w + 2) | ((ull)(a.w != 0.f)) << (4 * w + 3);
        }
    } else {
        const ull* p = (const ull*)mask + u * 8;
        #pragma unroll
        for (int w = 0; w < 8; ++w) {
            ull v = p[w];
            #pragma unroll
            for (int b8 = 0; b8 < 8; ++b8)
                bits |= ((ull)(((v >> (8 * b8)) & 0xffull) != 0)) << (8 * w + b8);
        }
    }
    g_maskBits[u] = bits;
}

// ---------------- K/V fp16 split precompute (K single, V hi/lo) ----------
__global__ __launch_bounds__(256)
void kvsplit_kernel(const float* __restrict__ K, const float* __restrict__ V)
{
    size_t i4 = (size_t)blockIdx.x * 256 + threadIdx.x;   // float4 index
    {
        float4 v = ((const float4*)K)[i4];
        ((uint2*)g_KVsp[0])[i4] = make_uint2(packh2(v.x, v.y), packh2(v.z, v.w));
    }
    {
        float4 v = ((const float4*)V)[i4];
        __half2 h01 = __floats2half2_rn(v.x, v.y);
        __half2 h23 = __floats2half2_rn(v.z, v.w);
        ((uint2*)g_KVsp[1])[i4] = make_uint2(h2bits(h01), h2bits(h23));
        ((uint2*)g_KVsp[2])[i4] = make_uint2(
            packh2(v.x - __low2float(h01), v.y - __high2float(h01)),
            packh2(v.z - __low2float(h23), v.w - __high2float(h23)));
    }
}

// ---------------- HMMA GEMM: C[M x 512] = A[M x 512] * B[512 x 512] --------
#define GLA 40
#define GLB 72

__global__ __launch_bounds__(128, 2)
void gemm_mma_kernel(const float* __restrict__ A, const float* __restrict__ Bm,
                     float* __restrict__ C)
{
    __shared__ __align__(16) __nv_bfloat16 sAh[128 * GLA], sAl[128 * GLA];
    __shared__ __align__(16) __nv_bfloat16 sBh[32 * GLB], sBl[32 * GLB];

    const int tid = threadIdx.x;
    const int warp = tid >> 5, lane = tid & 31;
    const int g = lane >> 3, lrow = lane & 7;
    const int mbase = blockIdx.x * 128, nbase = blockIdx.y * 64;

    float Ca[2][8][4];
    #pragma unroll
    for (int i = 0; i < 2; ++i)
        #pragma unroll
        for (int j = 0; j < 8; ++j)
            #pragma unroll
            for (int r = 0; r < 4; ++r) Ca[i][j][r] = 0.f;

    const int arow = warp * 32 + (g & 1) * 8 + lrow;
    const int acol = (g >> 1) * 8;
    const uint32_t bOff = (uint32_t)(((g & 1) * 8 + lrow) * GLB + (g >> 1) * 8) * 2;
    const uint32_t uBh = smem_to_u32(sBh), uBl = smem_to_u32(sBl);

    #pragma unroll 1
    for (int kk = 0; kk < 512; kk += 32) {
        __syncthreads();
        {
            const float4* ar = (const float4*)(A + (size_t)(mbase + tid) * 512 + kk);
            uint32_t* ah = (uint32_t*)(sAh + tid * GLA);
            uint32_t* al = (uint32_t*)(sAl + tid * GLA);
            #pragma unroll
            for (int i = 0; i < 8; ++i) {
                float4 v = ar[i];
                uint32_t h0 = cvt2(v.x, v.y), h1 = cvt2(v.z, v.w);
                ah[2 * i] = h0; ah[2 * i + 1] = h1;
                al[2 * i] = cvt2(v.x - lof(h0), v.y - hif(h0));
                al[2 * i + 1] = cvt2(v.z - lof(h1), v.w - hif(h1));
            }
        }
        {
            int br = tid >> 2, bc = (tid & 3) * 16;
            const float4* bp = (const float4*)(Bm + (size_t)(kk + br) * 512 + nbase + bc);
            uint32_t* bh = (uint32_t*)(sBh + br * GLB + bc);
            uint32_t* bl = (uint32_t*)(sBl + br * GLB + bc);
            #pragma unroll
            for (int i = 0; i < 4; ++i) {
                float4 v = bp[i];
                uint32_t h0 = cvt2(v.x, v.y), h1 = cvt2(v.z, v.w);
                bh[2 * i] = h0; bh[2 * i + 1] = h1;
                bl[2 * i] = cvt2(v.x - lof(h0), v.y - hif(h0));
                bl[2 * i + 1] = cvt2(v.z - lof(h1), v.w - hif(h1));
            }
        }
        __syncthreads();

        uint32_t Ah[2][2][4], Al[2][2][4];
        #pragma unroll
        for (int i = 0; i < 2; ++i)
            #pragma unroll
            for (int kb = 0; kb < 2; ++kb) {
                ldsm_x4(Ah[i][kb], smem_to_u32(sAh + (arow + i * 16) * GLA + acol + kb * 16));
                ldsm_x4(Al[i][kb], smem_to_u32(sAl + (arow + i * 16) * GLA + acol + kb * 16));
            }

        #pragma unroll
        for (int np = 0; np < 4; ++np) {
            #pragma unroll
            for (int kb = 0; kb < 2; ++kb) {
                uint32_t Bh[4], Bl[4];
                uint32_t off = (uint32_t)(kb * 16 * GLB + np * 16) * 2;
                ldsm_x4_t(Bh, uBh + off + bOff);
                ldsm_x4_t(Bl, uBl + off + bOff);
                #pragma unroll
                for (int i = 0; i < 2; ++i) mma_bf16(Ca[i][2 * np], Ah[i][kb], Bh[0], Bh[1]);
                #pragma unroll
                for (int i = 0; i < 2; ++i) mma_bf16(Ca[i][2 * np + 1], Ah[i][kb], Bh[2], Bh[3]);
                #pragma unroll
                for (int i = 0; i < 2; ++i) mma_bf16(Ca[i][2 * np], Ah[i][kb], Bl[0], Bl[1]);
                #pragma unroll
                for (int i = 0; i < 2; ++i) mma_bf16(Ca[i][2 * np + 1], Ah[i][kb], Bl[2], Bl[3]);
                #pragma unroll
                for (int i = 0; i < 2; ++i) mma_bf16(Ca[i][2 * np], Al[i][kb], Bh[0], Bh[1]);
                #pragma unroll
                for (int i = 0; i < 2; ++i) mma_bf16(Ca[i][2 * np + 1], Al[i][kb], Bh[2], Bh[3]);
            }
        }
    }

    #pragma unroll
    for (int i = 0; i < 2; ++i) {
        int r0 = mbase + warp * 32 + i * 16 + (lane >> 2);
        float* c0 = C + (size_t)r0 * 512 + nbase;
        float* c1 = c0 + (size_t)8 * 512;
        #pragma unroll
        for (int nb = 0; nb < 8; ++nb) {
            int d = nb * 8 + (lane & 3) * 2;
            *(float2*)(c0 + d) = make_float2(Ca[i][nb][0], Ca[i][nb][1]);
            *(float2*)(c1 + d) = make_float2(Ca[i][nb][2], Ca[i][nb][3]);
        }
    }
}

// ---------------- HMMA flash attention (fp16, cp.async double buffer) ------
// Planes per buffer: K | Vh | Vl ; two buffers. Q staged transiently.
#define LST 72
#define TS (64 * LST)            // elems per plane
#define PLB (TS * 2)             // plane bytes
#define BUFB (3 * PLB)           // buffer bytes

__global__ __launch_bounds__(128, 2)
void attn_mma_kernel(const ull* __restrict__ mbits,
                     const float* __restrict__ Q, float* __restrict__ O)
{
    extern __shared__ __align__(16) __half dyn[];   // 6 planes = 2 buffers

    const int b = blockIdx.z, h = blockIdx.y;
    const int qbase = blockIdx.x * 128;
    const int tid = threadIdx.x;
    const int warp = tid >> 5, lane = tid & 31;
    const int g = lane >> 3, lrow = lane & 7;

    // ---- stage Q (scaled 1/8, fp16 hi/lo) transiently:
    // hi rows 0-63 -> plane0, 64-127 -> plane1 ; lo -> planes 3,4
    {
        const float4* qr = (const float4*)(Q + (size_t)(b * SS + qbase + tid) * EE + h * DD);
        __half* bh = dyn + (tid >= 64 ? TS : 0) + (tid & 63) * LST;
        uint32_t* dh = (uint32_t*)bh;
        uint32_t* dl = (uint32_t*)(bh + 3 * TS);
        #pragma unroll
        for (int i = 0; i < 16; ++i) {
            float4 v = qr[i];
            v.x *= 0.125f; v.y *= 0.125f; v.z *= 0.125f; v.w *= 0.125f;
            __half2 h01 = __floats2half2_rn(v.x, v.y);
            __half2 h23 = __floats2half2_rn(v.z, v.w);
            dh[2 * i] = h2bits(h01); dh[2 * i + 1] = h2bits(h23);
            dl[2 * i] = packh2(v.x - __low2float(h01), v.y - __high2float(h01));
            dl[2 * i + 1] = packh2(v.z - __low2float(h23), v.w - __high2float(h23));
        }
    }
    __syncthreads();

    // ---- persistent Q A-fragments (hi/lo) ----
    uint32_t Qh[2][4][4], Ql[2][4][4];
    {
        const __half* bh = (warp < 2) ? dyn : dyn + TS;
        const int rowbase = (warp & 1) * 32;
        const int arow = rowbase + (g & 1) * 8 + lrow;
        const int acol = (g >> 1) * 8;
        #pragma unroll
        for (int i = 0; i < 2; ++i)
            #pragma unroll
            for (int kb = 0; kb < 4; ++kb) {
                ldsm_x4(Qh[i][kb], smem_to_u32(bh + (arow + i * 16) * LST + acol + kb * 16));
                ldsm_x4(Ql[i][kb], smem_to_u32(bh + 3 * TS + (arow + i * 16) * LST + acol + kb * 16));
            }
    }
    __syncthreads();   // all Q frags in regs before buffers get overwritten

    float Oa[2][8][4];
    #pragma unroll
    for (int i = 0; i < 2; ++i)
        #pragma unroll
        for (int j = 0; j < 8; ++j)
            #pragma unroll
            for (int r = 0; r < 4; ++r) Oa[i][j][r] = 0.f;
    float lsum[4] = {0.f, 0.f, 0.f, 0.f};

    const uint32_t uB = smem_to_u32(dyn);
    const uint32_t kOff = (uint32_t)(((g >> 1) * 8 + lrow) * LST + (g & 1) * 8) * 2;
    const uint32_t vOff = (uint32_t)(((g & 1) * 8 + lrow) * LST + (g >> 1) * 8) * 2;
    const ull* mrow = mbits + (size_t)(b * SS + qbase + warp * 32) * (SS / 64);

    // cp.async stage of one K/V tile (3 planes) into buffer `sel`
    const int sidx = tid;   // 12 segments per thread
    auto stage = [&](int kt, int sel) {
        uint32_t dbase = uB + sel * BUFB;
        #pragma unroll
        for (int j = 0; j < 12; ++j) {
            int idx = sidx + 128 * j;        // 0..1535
            int plane = idx >> 9;            // 0..2
            int rem = idx & 511;
            int row = rem >> 3, seg = rem & 7;
            const __half* src = g_KVsp[plane] +
                ((size_t)(b * SS + kt + row) * HH + h) * DD + seg * 8;
            uint32_t dst = dbase + (uint32_t)(plane * TS + row * LST + seg * 8) * 2;
            cp_async16(dst, src);
        }
        CP_COMMIT();
    };

    stage(0, 0);

    #pragma unroll 1
    for (int t = 0; t < SS / 64; ++t) {
        CP_WAIT0();
        __syncthreads();                    // tile t visible; prior reads done
        if (t + 1 < SS / 64) stage((t + 1) * 64, (t + 1) & 1);

        const uint32_t ubase = uB + (t & 1) * BUFB;
        const uint32_t uK = ubase, uVh = ubase + PLB, uVl = ubase + 2 * PLB;

        // ---- S = Q K^T (2-term: Qh*K + Ql*K) ----
        float S[2][8][4];
        #pragma unroll
        for (int i = 0; i < 2; ++i)
            #pragma unroll
            for (int j = 0; j < 8; ++j)
                #pragma unroll
                for (int r = 0; r < 4; ++r) S[i][j][r] = 0.f;

        #pragma unroll
        for (int np = 0; np < 4; ++np) {
            #pragma unroll
            for (int kb = 0; kb < 4; ++kb) {
                uint32_t Bk[4];
                uint32_t off = (uint32_t)(np * 16 * LST + kb * 16) * 2;
                ldsm_x4(Bk, uK + off + kOff);
                #pragma unroll
                for (int i = 0; i < 2; ++i) mma_f16(S[i][2 * np], Qh[i][kb], Bk[0], Bk[1]);
                #pragma unroll
                for (int i = 0; i < 2; ++i) mma_f16(S[i][2 * np + 1], Qh[i][kb], Bk[2], Bk[3]);
                #pragma unroll
                for (int i = 0; i < 2; ++i) mma_f16(S[i][2 * np], Ql[i][kb], Bk[0], Bk[1]);
                #pragma unroll
                for (int i = 0; i < 2; ++i) mma_f16(S[i][2 * np + 1], Ql[i][kb], Bk[2], Bk[3]);
            }
        }

        // ---- softmax (masked -> 0) + pack P single-term fp16 ----
        uint32_t Ph[2][4][4];
        #pragma unroll
        for (int i = 0; i < 2; ++i) {
            ull mw0 = mrow[(size_t)(i * 16 + (lane >> 2)) * (SS / 64) + t];
            ull mw1 = mrow[(size_t)(i * 16 + 8 + (lane >> 2)) * (SS / 64) + t];
            #pragma unroll
            for (int nb = 0; nb < 8; ++nb) {
                int p0 = nb * 8 + (lane & 3) * 2;
                float e0 = ((mw0 >> p0) & 1ull) ? 0.f : __expf(S[i][nb][0]);
                float e1 = ((mw0 >> (p0 + 1)) & 1ull) ? 0.f : __expf(S[i][nb][1]);
                float e2 = ((mw1 >> p0) & 1ull) ? 0.f : __expf(S[i][nb][2]);
                float e3 = ((mw1 >> (p0 + 1)) & 1ull) ? 0.f : __expf(S[i][nb][3]);
                lsum[i * 2] += e0 + e1;
                lsum[i * 2 + 1] += e2 + e3;
                int kb = nb >> 1, sub = (nb & 1) * 2;
                Ph[i][kb][sub] = packh2(e0, e1);
                Ph[i][kb][sub + 1] = packh2(e2, e3);
            }
        }

        // ---- O += P V (P single; V hi/lo) ----
        #pragma unroll
        for (int dp = 0; dp < 4; ++dp) {
            #pragma unroll
            for (int kb = 0; kb < 4; ++kb) {
                uint32_t Bh[4], Bl[4];
                uint32_t off = (uint32_t)(kb * 16 * LST + dp * 16) * 2;
                ldsm_x4_t(Bh, uVh + off + vOff);
                ldsm_x4_t(Bl, uVl + off + vOff);
                #pragma unroll
                for (int i = 0; i < 2; ++i) mma_f16(Oa[i][2 * dp], Ph[i][kb], Bh[0], Bh[1]);
                #pragma unroll
                for (int i = 0; i < 2; ++i) mma_f16(Oa[i][2 * dp + 1], Ph[i][kb], Bh[2], Bh[3]);
                #pragma unroll
                for (int i = 0; i < 2; ++i) mma_f16(Oa[i][2 * dp], Ph[i][kb], Bl[0], Bl[1]);
                #pragma unroll
                for (int i = 0; i < 2; ++i) mma_f16(Oa[i][2 * dp + 1], Ph[i][kb], Bl[2], Bl[3]);
            }
        }
    }

    // ---- normalize + store ----
    #pragma unroll
    for (int i = 0; i < 4; ++i) {
        lsum[i] += __shfl_xor_sync(0xffffffffu, lsum[i], 1);
        lsum[i] += __shfl_xor_sync(0xffffffffu, lsum[i], 2);
    }
    #pragma unroll
    for (int i = 0; i < 2; ++i) {
        float inv0 = 1.f / lsum[i * 2];
        float inv1 = 1.f / lsum[i * 2 + 1];
        int r0 = qbase + warp * 32 + i * 16 + (lane >> 2);
        float* o0 = O + (size_t)(b * SS + r0) * EE + h * DD;
        float* o1 = o0 + (size_t)8 * EE;
        #pragma unroll
        for (int nb = 0; nb < 8; ++nb) {
            int d = nb * 8 + (lane & 3) * 2;
            *(float2*)(o0 + d) = make_float2(Oa[i][nb][0] * inv0, Oa[i][nb][1] * inv0);
            *(float2*)(o1 + d) = make_float2(Oa[i][nb][2] * inv1, Oa[i][nb][3] * inv1);
        }
    }
}

// ---------------- launch ----------------
extern "C" void kernel_launch(void* const* d_in, const int* in_sizes, int n_in,
                              void* d_out, int out_size)
{
    const float* inputs = (const float*)d_in[0];
    const float* keys = (const float*)d_in[1];
    const float* values = (const float*)d_in[2];
    const float* wq = (const float*)d_in[3];
    const float* wo = (const float*)d_in[4];
    const void* mask_raw = d_in[5];
    float* out = (float*)d_out;

    float* qbuf; float* aobuf; ull* mbits;
    cudaGetSymbolAddress((void**)&qbuf, g_Q);
    cudaGetSymbolAddress((void**)&aobuf, g_AO);
    cudaGetSymbolAddress((void**)&mbits, g_maskBits);

    static int attr_set = 0;
    if (!attr_set) {
        cudaFuncSetAttribute(attn_mma_kernel,
                             cudaFuncAttributeMaxDynamicSharedMemorySize, 2 * BUFB);
        attr_set = 1;
    }

    detect_mask_kernel<<<1, 256>>>((const unsigned int*)mask_raw);
    bitpack_mask_kernel<<<(BB * SS * SS / 64) / 256, 256>>>(mask_raw);
    kvsplit_kernel<<<(int)(NKV / 4 / 256), 256>>>(keys, values);

    dim3 ggrid(32, 8);
    gemm_mma_kernel<<<ggrid, 128>>>(inputs, wq, qbuf);
    attn_mma_kernel<<<dim3(SS / 128, HH, BB), 128, 2 * BUFB>>>(mbits, qbuf, aobuf);
    gemm_mma_kernel<<<ggrid, 128>>>(aobuf, wo, out);
}

// round 13
// speedup vs baseline: 2.4921x; 1.1274x over previous
#include <cuda_runtime.h>
#include <cuda_bf16.h>
#include <cuda_fp16.h>
#include <cstdint>

#define BB 2
#define SS 2048
#define EE 512
#define HH 8
#define DD 64
#define NKV ((size_t)BB * SS * HH * DD)   // 2097152
#define NAC ((size_t)BB * SS * EE)        // 2097152

typedef unsigned long long ull;

// ---------------- fp16 helpers ----------------
__device__ __forceinline__ uint32_t h2bits(__half2 h) {
    uint32_t u; *(__half2*)&u = h; return u;
}
__device__ __forceinline__ uint32_t packh2(float lo, float hi) {
    return h2bits(__floats2half2_rn(lo, hi));
}
__device__ __forceinline__ uint32_t smem_to_u32(const void* p) {
    uint32_t a; asm("{ .reg .u64 t; cvta.to.shared.u64 t, %1; cvt.u32.u64 %0, t; }" : "=r"(a) : "l"(p)); return a;
}

// ---------------- mma.sync + ldmatrix + cp.async (baseline PTX) ----------
__device__ __forceinline__ void mma_f16(float* c, const uint32_t* a, uint32_t b0, uint32_t b1) {
    asm volatile("mma.sync.aligned.m16n8k16.row.col.f32.f16.f16.f32 "
        "{%0,%1,%2,%3}, {%4,%5,%6,%7}, {%8,%9}, {%0,%1,%2,%3};"
        : "+f"(c[0]), "+f"(c[1]), "+f"(c[2]), "+f"(c[3])
        : "r"(a[0]), "r"(a[1]), "r"(a[2]), "r"(a[3]), "r"(b0), "r"(b1));
}
__device__ __forceinline__ void ldsm_x4(uint32_t* r, uint32_t addr) {
    asm volatile("ldmatrix.sync.aligned.m8n8.x4.shared.b16 {%0,%1,%2,%3}, [%4];"
        : "=r"(r[0]), "=r"(r[1]), "=r"(r[2]), "=r"(r[3]) : "r"(addr));
}
__device__ __forceinline__ void ldsm_x4_t(uint32_t* r, uint32_t addr) {
    asm volatile("ldmatrix.sync.aligned.m8n8.x4.trans.shared.b16 {%0,%1,%2,%3}, [%4];"
        : "=r"(r[0]), "=r"(r[1]), "=r"(r[2]), "=r"(r[3]) : "r"(addr));
}
__device__ __forceinline__ void cp_async16(uint32_t dst, const void* src) {
    asm volatile("cp.async.ca.shared.global [%0], [%1], 16;" :: "r"(dst), "l"(src) : "memory");
}
#define CP_COMMIT() asm volatile("cp.async.commit_group;" ::: "memory")
#define CP_WAIT0()  asm volatile("cp.async.wait_group 0;" ::: "memory")

// ---------------- scratch ----------------
__device__ float g_Q[NAC];                 // projected queries (fp32)
__device__ __half g_AOh[NAC], g_AOl[NAC];  // attn output hi/lo planes
__device__ __half g_INh[NAC], g_INl[NAC];  // inputs hi/lo planes
__device__ __half g_W[2][512 * 512];       // wq, wo single fp16 planes
__device__ ull g_maskBits[(size_t)BB * SS * SS / 64];
__device__ int g_maskKind;
__device__ __half g_KVsp[3][NKV];          // fp16 planes: K, Vh, Vl

// ---------------- mask dtype detect + bitpack ----------------
__global__ void detect_mask_kernel(const unsigned int* __restrict__ w)
{
    int i32ok = 1, f32ok = 1;
    for (int i = threadIdx.x; i < 16384; i += 256) {
        unsigned int v = w[i];
        if (v > 1u) i32ok = 0;
        if (v != 0u && v != 0x3F800000u) f32ok = 0;
    }
    i32ok = __syncthreads_and(i32ok);
    f32ok = __syncthreads_and(f32ok);
    if (threadIdx.x == 0) g_maskKind = i32ok ? 1 : (f32ok ? 2 : 0);
}

__global__ __launch_bounds__(256)
void bitpack_mask_kernel(const void* __restrict__ mask)
{
    size_t u = (size_t)blockIdx.x * 256 + threadIdx.x;
    int kind = g_maskKind;
    ull bits = 0;
    if (kind == 1) {
        const int4* p = (const int4*)mask + u * 16;
        #pragma unroll
        for (int w = 0; w < 16; ++w) {
            int4 a = p[w];
            bits |= ((ull)(a.x != 0)) << (4 * w) | ((ull)(a.y != 0)) << (4 * w + 1) |
                    ((ull)(a.z != 0)) << (4 * w + 2) | ((ull)(a.w != 0)) << (4 * w + 3);
        }
    } else if (kind == 2) {
        const float4* p = (const float4*)mask + u * 16;
        #pragma unroll
        for (int w = 0; w < 16; ++w) {
            float4 a = p[w];
            bits |= ((ull)(a.x != 0.f)) << (4 * w) | ((ull)(a.y != 0.f)) << (4 * w + 1) |
                    ((ull)(a.z != 0.f)) << (4 * w + 2) | ((ull)(a.w != 0.f)) << (4 * w + 3);
        }
    } else {
        const ull* p = (const ull*)mask + u * 8;
        #pragma unroll
        for (int w = 0; w < 8; ++w) {
            ull v = p[w];
            #pragma unroll
            for (int b8 = 0; b8 < 8; ++b8)
                bits |= ((ull)(((v >> (8 * b8)) & 0xffull) != 0)) << (8 * w + b8);
        }
    }
    g_maskBits[u] = bits;
}

// ---------------- precompute: K/V planes, weight planes, input planes ------
__global__ __launch_bounds__(256)
void kvsplit_kernel(const float* __restrict__ K, const float* __restrict__ V)
{
    size_t i4 = (size_t)blockIdx.x * 256 + threadIdx.x;
    {
        float4 v = ((const float4*)K)[i4];
        ((uint2*)g_KVsp[0])[i4] = make_uint2(packh2(v.x, v.y), packh2(v.z, v.w));
    }
    {
        float4 v = ((const float4*)V)[i4];
        __half2 h01 = __floats2half2_rn(v.x, v.y);
        __half2 h23 = __floats2half2_rn(v.z, v.w);
        ((uint2*)g_KVsp[1])[i4] = make_uint2(h2bits(h01), h2bits(h23));
        ((uint2*)g_KVsp[2])[i4] = make_uint2(
            packh2(v.x - __low2float(h01), v.y - __high2float(h01)),
            packh2(v.z - __low2float(h23), v.w - __high2float(h23)));
    }
}

__global__ __launch_bounds__(256)
void wsplit_kernel(const float* __restrict__ wq, const float* __restrict__ wo)
{
    size_t i4 = (size_t)blockIdx.x * 256 + threadIdx.x;   // float4 index, 65536 total
    {
        float4 v = ((const float4*)wq)[i4];
        ((uint2*)g_W[0])[i4] = make_uint2(packh2(v.x, v.y), packh2(v.z, v.w));
    }
    {
        float4 v = ((const float4*)wo)[i4];
        ((uint2*)g_W[1])[i4] = make_uint2(packh2(v.x, v.y), packh2(v.z, v.w));
    }
}

__global__ __launch_bounds__(256)
void insplit_kernel(const float* __restrict__ A)
{
    size_t i4 = (size_t)blockIdx.x * 256 + threadIdx.x;
    float4 v = ((const float4*)A)[i4];
    __half2 h01 = __floats2half2_rn(v.x, v.y);
    __half2 h23 = __floats2half2_rn(v.z, v.w);
    ((uint2*)g_INh)[i4] = make_uint2(h2bits(h01), h2bits(h23));
    ((uint2*)g_INl)[i4] = make_uint2(
        packh2(v.x - __low2float(h01), v.y - __high2float(h01)),
        packh2(v.z - __low2float(h23), v.w - __high2float(h23)));
}

// ---------------- fp16 HMMA GEMM, cp.async double-buffered -----------------
// C[Mx512] = (Ah+Al)[Mx512] * W[512x512]; A hi/lo planes, W single plane.
#define GLA 40
#define GLB 72
#define GA_PL (128 * GLA)                 // A plane elems per buffer
#define GB_OFF (2 * GA_PL)                // B offset (elems) within buffer
#define GBUF (GB_OFF + 32 * GLB)          // buffer elems
#define GBUFB (GBUF * 2)                  // buffer bytes (25088)

__global__ __launch_bounds__(128, 2)
void gemm_fp16_kernel(const __half* __restrict__ Ah, const __half* __restrict__ Al,
                      const __half* __restrict__ W, float* __restrict__ C)
{
    extern __shared__ __align__(16) __half gdyn[];

    const int tid = threadIdx.x;
    const int warp = tid >> 5, lane = tid & 31;
    const int g = lane >> 3, lrow = lane & 7;
    const int mbase = blockIdx.x * 128, nbase = blockIdx.y * 64;

    float Ca[2][8][4];
    #pragma unroll
    for (int i = 0; i < 2; ++i)
        #pragma unroll
        for (int j = 0; j < 8; ++j)
            #pragma unroll
            for (int r = 0; r < 4; ++r) Ca[i][j][r] = 0.f;

    const uint32_t uS = smem_to_u32(gdyn);
    const int arow = warp * 32 + (g & 1) * 8 + lrow;
    const int acol = (g >> 1) * 8;
    const uint32_t bOff = (uint32_t)(((g & 1) * 8 + lrow) * GLB + (g >> 1) * 8) * 2;

    auto stage = [&](int kk, int sel) {
        uint32_t dbase = uS + sel * GBUFB;
        // A planes: 2 x 128 rows x 4 segs = 1024 segs (8 per thread)
        #pragma unroll
        for (int j = 0; j < 8; ++j) {
            int idx = tid + 128 * j;
            int plane = idx >> 9, rem = idx & 511;
            int row = rem >> 2, seg = rem & 3;
            const __half* src = (plane ? Al : Ah) + (size_t)(mbase + row) * 512 + kk + seg * 8;
            uint32_t dst = dbase + (uint32_t)(plane * GA_PL + row * GLA + seg * 8) * 2;
            cp_async16(dst, src);
        }
        // B: 32 rows x 8 segs = 256 segs (2 per thread)
        #pragma unroll
        for (int j = 0; j < 2; ++j) {
            int idx = tid + 128 * j;
            int row = idx >> 3, seg = idx & 7;
            const __half* src = W + (size_t)(kk + row) * 512 + nbase + seg * 8;
            uint32_t dst = dbase + (uint32_t)(GB_OFF + row * GLB + seg * 8) * 2;
            cp_async16(dst, src);
        }
        CP_COMMIT();
    };

    stage(0, 0);

    #pragma unroll 1
    for (int c = 0; c < 16; ++c) {
        CP_WAIT0();
        __syncthreads();
        if (c + 1 < 16) stage((c + 1) * 32, (c + 1) & 1);

        const uint32_t ubase = uS + (c & 1) * GBUFB;
        uint32_t Af[2][2][2][4];   // [plane][i][kb]
        #pragma unroll
        for (int p = 0; p < 2; ++p)
            #pragma unroll
            for (int i = 0; i < 2; ++i)
                #pragma unroll
                for (int kb = 0; kb < 2; ++kb)
                    ldsm_x4(Af[p][i][kb], ubase +
                        (uint32_t)(p * GA_PL + (arow + i * 16) * GLA + acol + kb * 16) * 2);

        #pragma unroll
        for (int np = 0; np < 4; ++np) {
            #pragma unroll
            for (int kb = 0; kb < 2; ++kb) {
                uint32_t Bk[4];
                uint32_t off = (uint32_t)(GB_OFF * 2) + (uint32_t)(kb * 16 * GLB + np * 16) * 2;
                ldsm_x4_t(Bk, ubase + off + bOff);
                #pragma unroll
                for (int i = 0; i < 2; ++i) mma_f16(Ca[i][2 * np], Af[0][i][kb], Bk[0], Bk[1]);
                #pragma unroll
                for (int i = 0; i < 2; ++i) mma_f16(Ca[i][2 * np + 1], Af[0][i][kb], Bk[2], Bk[3]);
                #pragma unroll
                for (int i = 0; i < 2; ++i) mma_f16(Ca[i][2 * np], Af[1][i][kb], Bk[0], Bk[1]);
                #pragma unroll
                for (int i = 0; i < 2; ++i) mma_f16(Ca[i][2 * np + 1], Af[1][i][kb], Bk[2], Bk[3]);
            }
        }
    }

    #pragma unroll
    for (int i = 0; i < 2; ++i) {
        int r0 = mbase + warp * 32 + i * 16 + (lane >> 2);
        float* c0 = C + (size_t)r0 * 512 + nbase;
        float* c1 = c0 + (size_t)8 * 512;
        #pragma unroll
        for (int nb = 0; nb < 8; ++nb) {
            int d = nb * 8 + (lane & 3) * 2;
            *(float2*)(c0 + d) = make_float2(Ca[i][nb][0], Ca[i][nb][1]);
            *(float2*)(c1 + d) = make_float2(Ca[i][nb][2], Ca[i][nb][3]);
        }
    }
}

// ---------------- HMMA flash attention (unchanged mainloop; fp16 plane out)
#define LST 72
#define TS (64 * LST)
#define PLB (TS * 2)
#define BUFB (3 * PLB)

__global__ __launch_bounds__(128, 2)
void attn_mma_kernel(const ull* __restrict__ mbits, const float* __restrict__ Q)
{
    extern __shared__ __align__(16) __half dyn[];

    const int b = blockIdx.z, h = blockIdx.y;
    const int qbase = blockIdx.x * 128;
    const int tid = threadIdx.x;
    const int warp = tid >> 5, lane = tid & 31;
    const int g = lane >> 3, lrow = lane & 7;

    // ---- stage Q (scaled 1/8, fp16 hi/lo) transiently ----
    {
        const float4* qr = (const float4*)(Q + (size_t)(b * SS + qbase + tid) * EE + h * DD);
        __half* bh = dyn + (tid >= 64 ? TS : 0) + (tid & 63) * LST;
        uint32_t* dh = (uint32_t*)bh;
        uint32_t* dl = (uint32_t*)(bh + 3 * TS);
        #pragma unroll
        for (int i = 0; i < 16; ++i) {
            float4 v = qr[i];
            v.x *= 0.125f; v.y *= 0.125f; v.z *= 0.125f; v.w *= 0.125f;
            __half2 h01 = __floats2half2_rn(v.x, v.y);
            __half2 h23 = __floats2half2_rn(v.z, v.w);
            dh[2 * i] = h2bits(h01); dh[2 * i + 1] = h2bits(h23);
            dl[2 * i] = packh2(v.x - __low2float(h01), v.y - __high2float(h01));
            dl[2 * i + 1] = packh2(v.z - __low2float(h23), v.w - __high2float(h23));
        }
    }
    __syncthreads();

    uint32_t Qh[2][4][4], Ql[2][4][4];
    {
        const __half* bh = (warp < 2) ? dyn : dyn + TS;
        const int rowbase = (warp & 1) * 32;
        const int arow = rowbase + (g & 1) * 8 + lrow;
        const int acol = (g >> 1) * 8;
        #pragma unroll
        for (int i = 0; i < 2; ++i)
            #pragma unroll
            for (int kb = 0; kb < 4; ++kb) {
                ldsm_x4(Qh[i][kb], smem_to_u32(bh + (arow + i * 16) * LST + acol + kb * 16));
                ldsm_x4(Ql[i][kb], smem_to_u32(bh + 3 * TS + (arow + i * 16) * LST + acol + kb * 16));
            }
    }
    __syncthreads();

    float Oa[2][8][4];
    #pragma unroll
    for (int i = 0; i < 2; ++i)
        #pragma unroll
        for (int j = 0; j < 8; ++j)
            #pragma unroll
            for (int r = 0; r < 4; ++r) Oa[i][j][r] = 0.f;
    float lsum[4] = {0.f, 0.f, 0.f, 0.f};

    const uint32_t uB = smem_to_u32(dyn);
    const uint32_t kOff = (uint32_t)(((g >> 1) * 8 + lrow) * LST + (g & 1) * 8) * 2;
    const uint32_t vOff = (uint32_t)(((g & 1) * 8 + lrow) * LST + (g >> 1) * 8) * 2;
    const ull* mrow = mbits + (size_t)(b * SS + qbase + warp * 32) * (SS / 64);

    auto stage = [&](int kt, int sel) {
        uint32_t dbase = uB + sel * BUFB;
        #pragma unroll
        for (int j = 0; j < 12; ++j) {
            int idx = tid + 128 * j;
            int plane = idx >> 9;
            int rem = idx & 511;
            int row = rem >> 3, seg = rem & 7;
            const __half* src = g_KVsp[plane] +
                ((size_t)(b * SS + kt + row) * HH + h) * DD + seg * 8;
            uint32_t dst = dbase + (uint32_t)(plane * TS + row * LST + seg * 8) * 2;
            cp_async16(dst, src);
        }
        CP_COMMIT();
    };

    stage(0, 0);

    #pragma unroll 1
    for (int t = 0; t < SS / 64; ++t) {
        CP_WAIT0();
        __syncthreads();
        if (t + 1 < SS / 64) stage((t + 1) * 64, (t + 1) & 1);

        const uint32_t ubase = uB + (t & 1) * BUFB;
        const uint32_t uK = ubase, uVh = ubase + PLB, uVl = ubase + 2 * PLB;

        float S[2][8][4];
        #pragma unroll
        for (int i = 0; i < 2; ++i)
            #pragma unroll
            for (int j = 0; j < 8; ++j)
                #pragma unroll
                for (int r = 0; r < 4; ++r) S[i][j][r] = 0.f;

        #pragma unroll
        for (int np = 0; np < 4; ++np) {
            #pragma unroll
            for (int kb = 0; kb < 4; ++kb) {
                uint32_t Bk[4];
                uint32_t off = (uint32_t)(np * 16 * LST + kb * 16) * 2;
                ldsm_x4(Bk, uK + off + kOff);
                #pragma unroll
                for (int i = 0; i < 2; ++i) mma_f16(S[i][2 * np], Qh[i][kb], Bk[0], Bk[1]);
                #pragma unroll
                for (int i = 0; i < 2; ++i) mma_f16(S[i][2 * np + 1], Qh[i][kb], Bk[2], Bk[3]);
                #pragma unroll
                for (int i = 0; i < 2; ++i) mma_f16(S[i][2 * np], Ql[i][kb], Bk[0], Bk[1]);
                #pragma unroll
                for (int i = 0; i < 2; ++i) mma_f16(S[i][2 * np + 1], Ql[i][kb], Bk[2], Bk[3]);
            }
        }

        uint32_t Ph[2][4][4];
        #pragma unroll
        for (int i = 0; i < 2; ++i) {
            ull mw0 = mrow[(size_t)(i * 16 + (lane >> 2)) * (SS / 64) + t];
            ull mw1 = mrow[(size_t)(i * 16 + 8 + (lane >> 2)) * (SS / 64) + t];
            #pragma unroll
            for (int nb = 0; nb < 8; ++nb) {
                int p0 = nb * 8 + (lane & 3) * 2;
                float e0 = ((mw0 >> p0) & 1ull) ? 0.f : __expf(S[i][nb][0]);
                float e1 = ((mw0 >> (p0 + 1)) & 1ull) ? 0.f : __expf(S[i][nb][1]);
                float e2 = ((mw1 >> p0) & 1ull) ? 0.f : __expf(S[i][nb][2]);
                float e3 = ((mw1 >> (p0 + 1)) & 1ull) ? 0.f : __expf(S[i][nb][3]);
                lsum[i * 2] += e0 + e1;
                lsum[i * 2 + 1] += e2 + e3;
                int kb = nb >> 1, sub = (nb & 1) * 2;
                Ph[i][kb][sub] = packh2(e0, e1);
                Ph[i][kb][sub + 1] = packh2(e2, e3);
            }
        }

        #pragma unroll
        for (int dp = 0; dp < 4; ++dp) {
            #pragma unroll
            for (int kb = 0; kb < 4; ++kb) {
                uint32_t Bh[4], Bl[4];
                uint32_t off = (uint32_t)(kb * 16 * LST + dp * 16) * 2;
                ldsm_x4_t(Bh, uVh + off + vOff);
                ldsm_x4_t(Bl, uVl + off + vOff);
                #pragma unroll
                for (int i = 0; i < 2; ++i) mma_f16(Oa[i][2 * dp], Ph[i][kb], Bh[0], Bh[1]);
                #pragma unroll
                for (int i = 0; i < 2; ++i) mma_f16(Oa[i][2 * dp + 1], Ph[i][kb], Bh[2], Bh[3]);
                #pragma unroll
                for (int i = 0; i < 2; ++i) mma_f16(Oa[i][2 * dp], Ph[i][kb], Bl[0], Bl[1]);
                #pragma unroll
                for (int i = 0; i < 2; ++i) mma_f16(Oa[i][2 * dp + 1], Ph[i][kb], Bl[2], Bl[3]);
            }
        }
    }

    // ---- normalize + store as fp16 hi/lo planes ----
    #pragma unroll
    for (int i = 0; i < 4; ++i) {
        lsum[i] += __shfl_xor_sync(0xffffffffu, lsum[i], 1);
        lsum[i] += __shfl_xor_sync(0xffffffffu, lsum[i], 2);
    }
    #pragma unroll
    for (int i = 0; i < 2; ++i) {
        float inv0 = 1.f / lsum[i * 2];
        float inv1 = 1.f / lsum[i * 2 + 1];
        int r0 = qbase + warp * 32 + i * 16 + (lane >> 2);
        size_t base0 = (size_t)(b * SS + r0) * EE + h * DD;
        size_t base1 = base0 + (size_t)8 * EE;
        #pragma unroll
        for (int nb = 0; nb < 8; ++nb) {
            int d = nb * 8 + (lane & 3) * 2;
            float v0 = Oa[i][nb][0] * inv0, v1 = Oa[i][nb][1] * inv0;
            float v2 = Oa[i][nb][2] * inv1, v3 = Oa[i][nb][3] * inv1;
            __half2 h01 = __floats2half2_rn(v0, v1);
            __half2 h23 = __floats2half2_rn(v2, v3);
            *(uint32_t*)(g_AOh + base0 + d) = h2bits(h01);
            *(uint32_t*)(g_AOl + base0 + d) =
                packh2(v0 - __low2float(h01), v1 - __high2float(h01));
            *(uint32_t*)(g_AOh + base1 + d) = h2bits(h23);
            *(uint32_t*)(g_AOl + base1 + d) =
                packh2(v2 - __low2float(h23), v3 - __high2float(h23));
        }
    }
}

// ---------------- launch ----------------
extern "C" void kernel_launch(void* const* d_in, const int* in_sizes, int n_in,
                              void* d_out, int out_size)
{
    const float* inputs = (const float*)d_in[0];
    const float* keys = (const float*)d_in[1];
    const float* values = (const float*)d_in[2];
    const float* wq = (const float*)d_in[3];
    const float* wo = (const float*)d_in[4];
    const void* mask_raw = d_in[5];
    float* out = (float*)d_out;

    float* qbuf; ull* mbits;
    __half *inh, *inl, *aoh, *aol, *w0, *w1;
    cudaGetSymbolAddress((void**)&qbuf, g_Q);
    cudaGetSymbolAddress((void**)&mbits, g_maskBits);
    cudaGetSymbolAddress((void**)&inh, g_INh);
    cudaGetSymbolAddress((void**)&inl, g_INl);
    cudaGetSymbolAddress((void**)&aoh, g_AOh);
    cudaGetSymbolAddress((void**)&aol, g_AOl);
    cudaGetSymbolAddress((void**)&w0, g_W);
    w1 = w0 + 512 * 512;

    static int attr_set = 0;
    if (!attr_set) {
        cudaFuncSetAttribute(attn_mma_kernel,
                             cudaFuncAttributeMaxDynamicSharedMemorySize, 2 * BUFB);
        cudaFuncSetAttribute(gemm_fp16_kernel,
                             cudaFuncAttributeMaxDynamicSharedMemorySize, 2 * GBUFB);
        attr_set = 1;
    }

    detect_mask_kernel<<<1, 256>>>((const unsigned int*)mask_raw);
    bitpack_mask_kernel<<<(BB * SS * SS / 64) / 256, 256>>>(mask_raw);
    kvsplit_kernel<<<(int)(NKV / 4 / 256), 256>>>(keys, values);
    wsplit_kernel<<<512 * 512 / 4 / 256, 256>>>(wq, wo);
    insplit_kernel<<<(int)(NAC / 4 / 256), 256>>>(inputs);

    dim3 ggrid(32, 8);
    gemm_fp16_kernel<<<ggrid, 128, 2 * GBUFB>>>(inh, inl, w0, qbuf);
    attn_mma_kernel<<<dim3(SS / 128, HH, BB), 128, 2 * BUFB>>>(mbits, qbuf);
    gemm_fp16_kernel<<<ggrid, 128, 2 * GBUFB>>>(aoh, aol, w1, out);
}

// round 14
// speedup vs baseline: 3.3463x; 1.3427x over previous
#include <cuda_runtime.h>
#include <cuda_bf16.h>
#include <cuda_fp16.h>
#include <cstdint>

#define BB 2
#define SS 2048
#define EE 512
#define HH 8
#define DD 64
#define NKV ((size_t)BB * SS * HH * DD)   // 2097152
#define NAC ((size_t)BB * SS * EE)        // 2097152

typedef unsigned long long ull;

// ---------------- fp16 helpers ----------------
__device__ __forceinline__ uint32_t h2bits(__half2 h) {
    uint32_t u; *(__half2*)&u = h; return u;
}
__device__ __forceinline__ uint32_t packh2(float lo, float hi) {
    return h2bits(__floats2half2_rn(lo, hi));
}
__device__ __forceinline__ uint32_t smem_to_u32(const void* p) {
    uint32_t a; asm("{ .reg .u64 t; cvta.to.shared.u64 t, %1; cvt.u32.u64 %0, t; }" : "=r"(a) : "l"(p)); return a;
}

// ---------------- mma.sync + ldmatrix + cp.async (baseline PTX) ----------
__device__ __forceinline__ void mma_f16(float* c, const uint32_t* a, uint32_t b0, uint32_t b1) {
    asm volatile("mma.sync.aligned.m16n8k16.row.col.f32.f16.f16.f32 "
        "{%0,%1,%2,%3}, {%4,%5,%6,%7}, {%8,%9}, {%0,%1,%2,%3};"
        : "+f"(c[0]), "+f"(c[1]), "+f"(c[2]), "+f"(c[3])
        : "r"(a[0]), "r"(a[1]), "r"(a[2]), "r"(a[3]), "r"(b0), "r"(b1));
}
__device__ __forceinline__ void ldsm_x4(uint32_t* r, uint32_t addr) {
    asm volatile("ldmatrix.sync.aligned.m8n8.x4.shared.b16 {%0,%1,%2,%3}, [%4];"
        : "=r"(r[0]), "=r"(r[1]), "=r"(r[2]), "=r"(r[3]) : "r"(addr));
}
__device__ __forceinline__ void ldsm_x4_t(uint32_t* r, uint32_t addr) {
    asm volatile("ldmatrix.sync.aligned.m8n8.x4.trans.shared.b16 {%0,%1,%2,%3}, [%4];"
        : "=r"(r[0]), "=r"(r[1]), "=r"(r[2]), "=r"(r[3]) : "r"(addr));
}
__device__ __forceinline__ void cp_async16(uint32_t dst, const void* src) {
    asm volatile("cp.async.ca.shared.global [%0], [%1], 16;" :: "r"(dst), "l"(src) : "memory");
}
#define CP_COMMIT() asm volatile("cp.async.commit_group;" ::: "memory")
#define CP_WAIT0()  asm volatile("cp.async.wait_group 0;" ::: "memory")

// ---------------- scratch ----------------
__device__ float g_Q[NAC];                 // projected queries (fp32)
__device__ __half g_AOh[NAC], g_AOl[NAC];  // attn output hi/lo planes
__device__ __half g_INh[NAC], g_INl[NAC];  // inputs hi/lo planes
__device__ __half g_W[2][512 * 512];       // wq, wo single fp16 planes
__device__ ull g_maskBits[(size_t)BB * SS * SS / 64];
__device__ int g_maskKind;
__device__ __half g_KVsp[2][NKV];          // fp16 planes: K, V (single-term)

// ---------------- mask dtype detect + bitpack ----------------
__global__ void detect_mask_kernel(const unsigned int* __restrict__ w)
{
    int i32ok = 1, f32ok = 1;
    for (int i = threadIdx.x; i < 16384; i += 256) {
        unsigned int v = w[i];
        if (v > 1u) i32ok = 0;
        if (v != 0u && v != 0x3F800000u) f32ok = 0;
    }
    i32ok = __syncthreads_and(i32ok);
    f32ok = __syncthreads_and(f32ok);
    if (threadIdx.x == 0) g_maskKind = i32ok ? 1 : (f32ok ? 2 : 0);
}

__global__ __launch_bounds__(256)
void bitpack_mask_kernel(const void* __restrict__ mask)
{
    size_t u = (size_t)blockIdx.x * 256 + threadIdx.x;
    int kind = g_maskKind;
    ull bits = 0;
    if (kind == 1) {
        const int4* p = (const int4*)mask + u * 16;
        #pragma unroll
        for (int w = 0; w < 16; ++w) {
            int4 a = p[w];
            bits |= ((ull)(a.x != 0)) << (4 * w) | ((ull)(a.y != 0)) << (4 * w + 1) |
                    ((ull)(a.z != 0)) << (4 * w + 2) | ((ull)(a.w != 0)) << (4 * w + 3);
        }
    } else if (kind == 2) {
        const float4* p = (const float4*)mask + u * 16;
        #pragma unroll
        for (int w = 0; w < 16; ++w) {
            float4 a = p[w];
            bits |= ((ull)(a.x != 0.f)) << (4 * w) | ((ull)(a.y != 0.f)) << (4 * w + 1) |
                    ((ull)(a.z != 0.f)) << (4 * w + 2) | ((ull)(a.w != 0.f)) << (4 * w + 3);
        }
    } else {
        const ull* p = (const ull*)mask + u * 8;
        #pragma unroll
        for (int w = 0; w < 8; ++w) {
            ull v = p[w];
            #pragma unroll
            for (int b8 = 0; b8 < 8; ++b8)
                bits |= ((ull)(((v >> (8 * b8)) & 0xffull) != 0)) << (8 * w + b8);
        }
    }
    g_maskBits[u] = bits;
}

// ---------------- precompute: K/V, weight, input planes ------
__global__ __launch_bounds__(256)
void kvsplit_kernel(const float* __restrict__ K, const float* __restrict__ V)
{
    size_t i4 = (size_t)blockIdx.x * 256 + threadIdx.x;
    {
        float4 v = ((const float4*)K)[i4];
        ((uint2*)g_KVsp[0])[i4] = make_uint2(packh2(v.x, v.y), packh2(v.z, v.w));
    }
    {
        float4 v = ((const float4*)V)[i4];
        ((uint2*)g_KVsp[1])[i4] = make_uint2(packh2(v.x, v.y), packh2(v.z, v.w));
    }
}

__global__ __launch_bounds__(256)
void wsplit_kernel(const float* __restrict__ wq, const float* __restrict__ wo)
{
    size_t i4 = (size_t)blockIdx.x * 256 + threadIdx.x;
    {
        float4 v = ((const float4*)wq)[i4];
        ((uint2*)g_W[0])[i4] = make_uint2(packh2(v.x, v.y), packh2(v.z, v.w));
    }
    {
        float4 v = ((const float4*)wo)[i4];
        ((uint2*)g_W[1])[i4] = make_uint2(packh2(v.x, v.y), packh2(v.z, v.w));
    }
}

__global__ __launch_bounds__(256)
void insplit_kernel(const float* __restrict__ A)
{
    size_t i4 = (size_t)blockIdx.x * 256 + threadIdx.x;
    float4 v = ((const float4*)A)[i4];
    __half2 h01 = __floats2half2_rn(v.x, v.y);
    __half2 h23 = __floats2half2_rn(v.z, v.w);
    ((uint2*)g_INh)[i4] = make_uint2(h2bits(h01), h2bits(h23));
    ((uint2*)g_INl)[i4] = make_uint2(
        packh2(v.x - __low2float(h01), v.y - __high2float(h01)),
        packh2(v.z - __low2float(h23), v.w - __high2float(h23)));
}

// ---------------- fp16 HMMA GEMM, cp.async double-buffered (unchanged) -----
#define GLA 40
#define GLB 72
#define GA_PL (128 * GLA)
#define GB_OFF (2 * GA_PL)
#define GBUF (GB_OFF + 32 * GLB)
#define GBUFB (GBUF * 2)

__global__ __launch_bounds__(128, 2)
void gemm_fp16_kernel(const __half* __restrict__ Ah, const __half* __restrict__ Al,
                      const __half* __restrict__ W, float* __restrict__ C)
{
    extern __shared__ __align__(16) __half gdyn[];

    const int tid = threadIdx.x;
    const int warp = tid >> 5, lane = tid & 31;
    const int g = lane >> 3, lrow = lane & 7;
    const int mbase = blockIdx.x * 128, nbase = blockIdx.y * 64;

    float Ca[2][8][4];
    #pragma unroll
    for (int i = 0; i < 2; ++i)
        #pragma unroll
        for (int j = 0; j < 8; ++j)
            #pragma unroll
            for (int r = 0; r < 4; ++r) Ca[i][j][r] = 0.f;

    const uint32_t uS = smem_to_u32(gdyn);
    const int arow = warp * 32 + (g & 1) * 8 + lrow;
    const int acol = (g >> 1) * 8;
    const uint32_t bOff = (uint32_t)(((g & 1) * 8 + lrow) * GLB + (g >> 1) * 8) * 2;

    auto stage = [&](int kk, int sel) {
        uint32_t dbase = uS + sel * GBUFB;
        #pragma unroll
        for (int j = 0; j < 8; ++j) {
            int idx = tid + 128 * j;
            int plane = idx >> 9, rem = idx & 511;
            int row = rem >> 2, seg = rem & 3;
            const __half* src = (plane ? Al : Ah) + (size_t)(mbase + row) * 512 + kk + seg * 8;
            uint32_t dst = dbase + (uint32_t)(plane * GA_PL + row * GLA + seg * 8) * 2;
            cp_async16(dst, src);
        }
        #pragma unroll
        for (int j = 0; j < 2; ++j) {
            int idx = tid + 128 * j;
            int row = idx >> 3, seg = idx & 7;
            const __half* src = W + (size_t)(kk + row) * 512 + nbase + seg * 8;
            uint32_t dst = dbase + (uint32_t)(GB_OFF + row * GLB + seg * 8) * 2;
            cp_async16(dst, src);
        }
        CP_COMMIT();
    };

    stage(0, 0);

    #pragma unroll 1
    for (int c = 0; c < 16; ++c) {
        CP_WAIT0();
        __syncthreads();
        if (c + 1 < 16) stage((c + 1) * 32, (c + 1) & 1);

        const uint32_t ubase = uS + (c & 1) * GBUFB;
        uint32_t Af[2][2][2][4];
        #pragma unroll
        for (int p = 0; p < 2; ++p)
            #pragma unroll
            for (int i = 0; i < 2; ++i)
                #pragma unroll
                for (int kb = 0; kb < 2; ++kb)
                    ldsm_x4(Af[p][i][kb], ubase +
                        (uint32_t)(p * GA_PL + (arow + i * 16) * GLA + acol + kb * 16) * 2);

        #pragma unroll
        for (int np = 0; np < 4; ++np) {
            #pragma unroll
            for (int kb = 0; kb < 2; ++kb) {
                uint32_t Bk[4];
                uint32_t off = (uint32_t)(GB_OFF * 2) + (uint32_t)(kb * 16 * GLB + np * 16) * 2;
                ldsm_x4_t(Bk, ubase + off + bOff);
                #pragma unroll
                for (int i = 0; i < 2; ++i) mma_f16(Ca[i][2 * np], Af[0][i][kb], Bk[0], Bk[1]);
                #pragma unroll
                for (int i = 0; i < 2; ++i) mma_f16(Ca[i][2 * np + 1], Af[0][i][kb], Bk[2], Bk[3]);
                #pragma unroll
                for (int i = 0; i < 2; ++i) mma_f16(Ca[i][2 * np], Af[1][i][kb], Bk[0], Bk[1]);
                #pragma unroll
                for (int i = 0; i < 2; ++i) mma_f16(Ca[i][2 * np + 1], Af[1][i][kb], Bk[2], Bk[3]);
            }
        }
    }

    #pragma unroll
    for (int i = 0; i < 2; ++i) {
        int r0 = mbase + warp * 32 + i * 16 + (lane >> 2);
        float* c0 = C + (size_t)r0 * 512 + nbase;
        float* c1 = c0 + (size_t)8 * 512;
        #pragma unroll
        for (int nb = 0; nb < 8; ++nb) {
            int d = nb * 8 + (lane & 3) * 2;
            *(float2*)(c0 + d) = make_float2(Ca[i][nb][0], Ca[i][nb][1]);
            *(float2*)(c1 + d) = make_float2(Ca[i][nb][2], Ca[i][nb][3]);
        }
    }
}

// ---------------- HMMA flash attention, all-single-term fp16 ---------------
// Buffer planes: K | V ; two buffers. Q (hi only) staged transiently.
#define LST 72
#define TS (64 * LST)
#define PLB (TS * 2)
#define BUFB (2 * PLB)

__global__ __launch_bounds__(128, 2)
void attn_mma_kernel(const ull* __restrict__ mbits, const float* __restrict__ Q)
{
    extern __shared__ __align__(16) __half dyn[];   // 4 planes = 2 buffers

    const int b = blockIdx.z, h = blockIdx.y;
    const int qbase = blockIdx.x * 128;
    const int tid = threadIdx.x;
    const int warp = tid >> 5, lane = tid & 31;
    const int g = lane >> 3, lrow = lane & 7;

    // ---- stage Q (scaled 1/8, fp16 single): rows 0-63 -> plane0, 64-127 -> plane1
    {
        const float4* qr = (const float4*)(Q + (size_t)(b * SS + qbase + tid) * EE + h * DD);
        uint32_t* dh = (uint32_t*)(dyn + (tid >= 64 ? TS : 0) + (tid & 63) * LST);
        #pragma unroll
        for (int i = 0; i < 16; ++i) {
            float4 v = qr[i];
            dh[2 * i] = packh2(v.x * 0.125f, v.y * 0.125f);
            dh[2 * i + 1] = packh2(v.z * 0.125f, v.w * 0.125f);
        }
    }
    __syncthreads();

    // ---- persistent Q A-fragments ----
    uint32_t Qh[2][4][4];
    {
        const __half* bh = (warp < 2) ? dyn : dyn + TS;
        const int rowbase = (warp & 1) * 32;
        const int arow = rowbase + (g & 1) * 8 + lrow;
        const int acol = (g >> 1) * 8;
        #pragma unroll
        for (int i = 0; i < 2; ++i)
            #pragma unroll
            for (int kb = 0; kb < 4; ++kb)
                ldsm_x4(Qh[i][kb], smem_to_u32(bh + (arow + i * 16) * LST + acol + kb * 16));
    }
    __syncthreads();   // Q frags in regs before buffers are overwritten

    float Oa[2][8][4];
    #pragma unroll
    for (int i = 0; i < 2; ++i)
        #pragma unroll
        for (int j = 0; j < 8; ++j)
            #pragma unroll
            for (int r = 0; r < 4; ++r) Oa[i][j][r] = 0.f;
    float lsum[4] = {0.f, 0.f, 0.f, 0.f};

    const uint32_t uB = smem_to_u32(dyn);
    const uint32_t kOff = (uint32_t)(((g >> 1) * 8 + lrow) * LST + (g & 1) * 8) * 2;
    const uint32_t vOff = (uint32_t)(((g & 1) * 8 + lrow) * LST + (g >> 1) * 8) * 2;
    const ull* mrow = mbits + (size_t)(b * SS + qbase + warp * 32) * (SS / 64);

    // stage one K/V tile (2 planes) into buffer sel: 8 segs per thread
    auto stage = [&](int kt, int sel) {
        uint32_t dbase = uB + sel * BUFB;
        #pragma unroll
        for (int j = 0; j < 8; ++j) {
            int idx = tid + 128 * j;         // 0..1023
            int plane = idx >> 9;            // 0..1
            int rem = idx & 511;
            int row = rem >> 3, seg = rem & 7;
            const __half* src = g_KVsp[plane] +
                ((size_t)(b * SS + kt + row) * HH + h) * DD + seg * 8;
            uint32_t dst = dbase + (uint32_t)(plane * TS + row * LST + seg * 8) * 2;
            cp_async16(dst, src);
        }
        CP_COMMIT();
    };

    stage(0, 0);

    #pragma unroll 1
    for (int t = 0; t < SS / 64; ++t) {
        CP_WAIT0();
        __syncthreads();
        if (t + 1 < SS / 64) stage((t + 1) * 64, (t + 1) & 1);

        const uint32_t ubase = uB + (t & 1) * BUFB;
        const uint32_t uK = ubase, uV = ubase + PLB;

        // ---- S = Q K^T (single-term) ----
        float S[2][8][4];
        #pragma unroll
        for (int i = 0; i < 2; ++i)
            #pragma unroll
            for (int j = 0; j < 8; ++j)
                #pragma unroll
                for (int r = 0; r < 4; ++r) S[i][j][r] = 0.f;

        #pragma unroll
        for (int np = 0; np < 4; ++np) {
            #pragma unroll
            for (int kb = 0; kb < 4; ++kb) {
                uint32_t Bk[4];
                uint32_t off = (uint32_t)(np * 16 * LST + kb * 16) * 2;
                ldsm_x4(Bk, uK + off + kOff);
                #pragma unroll
                for (int i = 0; i < 2; ++i) mma_f16(S[i][2 * np], Qh[i][kb], Bk[0], Bk[1]);
                #pragma unroll
                for (int i = 0; i < 2; ++i) mma_f16(S[i][2 * np + 1], Qh[i][kb], Bk[2], Bk[3]);
            }
        }

        // ---- softmax (masked -> 0) + pack P single-term fp16 ----
        uint32_t Ph[2][4][4];
        #pragma unroll
        for (int i = 0; i < 2; ++i) {
            ull mw0 = mrow[(size_t)(i * 16 + (lane >> 2)) * (SS / 64) + t];
            ull mw1 = mrow[(size_t)(i * 16 + 8 + (lane >> 2)) * (SS / 64) + t];
            #pragma unroll
            for (int nb = 0; nb < 8; ++nb) {
                int p0 = nb * 8 + (lane & 3) * 2;
                float e0 = ((mw0 >> p0) & 1ull) ? 0.f : __expf(S[i][nb][0]);
                float e1 = ((mw0 >> (p0 + 1)) & 1ull) ? 0.f : __expf(S[i][nb][1]);
                float e2 = ((mw1 >> p0) & 1ull) ? 0.f : __expf(S[i][nb][2]);
                float e3 = ((mw1 >> (p0 + 1)) & 1ull) ? 0.f : __expf(S[i][nb][3]);
                lsum[i * 2] += e0 + e1;
                lsum[i * 2 + 1] += e2 + e3;
                int kb = nb >> 1, sub = (nb & 1) * 2;
                Ph[i][kb][sub] = packh2(e0, e1);
                Ph[i][kb][sub + 1] = packh2(e2, e3);
            }
        }

        // ---- O += P V (both single-term) ----
        #pragma unroll
        for (int dp = 0; dp < 4; ++dp) {
            #pragma unroll
            for (int kb = 0; kb < 4; ++kb) {
                uint32_t Bv[4];
                uint32_t off = (uint32_t)(kb * 16 * LST + dp * 16) * 2;
                ldsm_x4_t(Bv, uV + off + vOff);
                #pragma unroll
                for (int i = 0; i < 2; ++i) mma_f16(Oa[i][2 * dp], Ph[i][kb], Bv[0], Bv[1]);
                #pragma unroll
                for (int i = 0; i < 2; ++i) mma_f16(Oa[i][2 * dp + 1], Ph[i][kb], Bv[2], Bv[3]);
            }
        }
    }

    // ---- normalize + store as fp16 hi/lo planes ----
    #pragma unroll
    for (int i = 0; i < 4; ++i) {
        lsum[i] += __shfl_xor_sync(0xffffffffu, lsum[i], 1);
        lsum[i] += __shfl_xor_sync(0xffffffffu, lsum[i], 2);
    }
    #pragma unroll
    for (int i = 0; i < 2; ++i) {
        float inv0 = 1.f / lsum[i * 2];
        float inv1 = 1.f / lsum[i * 2 + 1];
        int r0 = qbase + warp * 32 + i * 16 + (lane >> 2);
        size_t base0 = (size_t)(b * SS + r0) * EE + h * DD;
        size_t base1 = base0 + (size_t)8 * EE;
        #pragma unroll
        for (int nb = 0; nb < 8; ++nb) {
            int d = nb * 8 + (lane & 3) * 2;
            float v0 = Oa[i][nb][0] * inv0, v1 = Oa[i][nb][1] * inv0;
            float v2 = Oa[i][nb][2] * inv1, v3 = Oa[i][nb][3] * inv1;
            __half2 h01 = __floats2half2_rn(v0, v1);
            __half2 h23 = __floats2half2_rn(v2, v3);
            *(uint32_t*)(g_AOh + base0 + d) = h2bits(h01);
            *(uint32_t*)(g_AOl + base0 + d) =
                packh2(v0 - __low2float(h01), v1 - __high2float(h01));
            *(uint32_t*)(g_AOh + base1 + d) = h2bits(h23);
            *(uint32_t*)(g_AOl + base1 + d) =
                packh2(v2 - __low2float(h23), v3 - __high2float(h23));
        }
    }
}

// ---------------- launch ----------------
extern "C" void kernel_launch(void* const* d_in, const int* in_sizes, int n_in,
                              void* d_out, int out_size)
{
    const float* inputs = (const float*)d_in[0];
    const float* keys = (const float*)d_in[1];
    const float* values = (const float*)d_in[2];
    const float* wq = (const float*)d_in[3];
    const float* wo = (const float*)d_in[4];
    const void* mask_raw = d_in[5];
    float* out = (float*)d_out;

    float* qbuf; ull* mbits;
    __half *inh, *inl, *aoh, *aol, *w0, *w1;
    cudaGetSymbolAddress((void**)&qbuf, g_Q);
    cudaGetSymbolAddress((void**)&mbits, g_maskBits);
    cudaGetSymbolAddress((void**)&inh, g_INh);
    cudaGetSymbolAddress((void**)&inl, g_INl);
    cudaGetSymbolAddress((void**)&aoh, g_AOh);
    cudaGetSymbolAddress((void**)&aol, g_AOl);
    cudaGetSymbolAddress((void**)&w0, g_W);
    w1 = w0 + 512 * 512;

    static int attr_set = 0;
    if (!attr_set) {
        cudaFuncSetAttribute(attn_mma_kernel,
                             cudaFuncAttributeMaxDynamicSharedMemorySize, 2 * BUFB);
        cudaFuncSetAttribute(gemm_fp16_kernel,
                             cudaFuncAttributeMaxDynamicSharedMemorySize, 2 * GBUFB);
        attr_set = 1;
    }

    detect_mask_kernel<<<1, 256>>>((const unsigned int*)mask_raw);
    bitpack_mask_kernel<<<(BB * SS * SS / 64) / 256, 256>>>(mask_raw);
    kvsplit_kernel<<<(int)(NKV / 4 / 256), 256>>>(keys, values);
    wsplit_kernel<<<512 * 512 / 4 / 256, 256>>>(wq, wo);
    insplit_kernel<<<(int)(NAC / 4 / 256), 256>>>(inputs);

    dim3 ggrid(32, 8);
    gemm_fp16_kernel<<<ggrid, 128, 2 * GBUFB>>>(inh, inl, w0, qbuf);
    attn_mma_kernel<<<dim3(SS / 128, HH, BB), 128, 2 * BUFB>>>(mbits, qbuf);
    gemm_fp16_kernel<<<ggrid, 128, 2 * GBUFB>>>(aoh, aol, w1, out);
}

// round 16
// speedup vs baseline: 3.4964x; 1.0449x over previous
#include <cuda_runtime.h>
#include <cuda_bf16.h>
#include <cuda_fp16.h>
#include <cstdint>

#define BB 2
#define SS 2048
#define EE 512
#define HH 8
#define DD 64
#define NKV ((size_t)BB * SS * HH * DD)   // 2097152
#define NAC ((size_t)BB * SS * EE)        // 2097152

typedef unsigned long long ull;

// ---------------- fp16 helpers ----------------
__device__ __forceinline__ uint32_t h2bits(__half2 h) {
    uint32_t u; *(__half2*)&u = h; return u;
}
__device__ __forceinline__ uint32_t packh2(float lo, float hi) {
    return h2bits(__floats2half2_rn(lo, hi));
}
__device__ __forceinline__ uint32_t smem_to_u32(const void* p) {
    uint32_t a; asm("{ .reg .u64 t; cvta.to.shared.u64 t, %1; cvt.u32.u64 %0, t; }" : "=r"(a) : "l"(p)); return a;
}

// ---------------- mma.sync + ldmatrix + cp.async (baseline PTX) ----------
__device__ __forceinline__ void mma_f16(float* c, const uint32_t* a, uint32_t b0, uint32_t b1) {
    asm volatile("mma.sync.aligned.m16n8k16.row.col.f32.f16.f16.f32 "
        "{%0,%1,%2,%3}, {%4,%5,%6,%7}, {%8,%9}, {%0,%1,%2,%3};"
        : "+f"(c[0]), "+f"(c[1]), "+f"(c[2]), "+f"(c[3])
        : "r"(a[0]), "r"(a[1]), "r"(a[2]), "r"(a[3]), "r"(b0), "r"(b1));
}
__device__ __forceinline__ void ldsm_x4(uint32_t* r, uint32_t addr) {
    asm volatile("ldmatrix.sync.aligned.m8n8.x4.shared.b16 {%0,%1,%2,%3}, [%4];"
        : "=r"(r[0]), "=r"(r[1]), "=r"(r[2]), "=r"(r[3]) : "r"(addr));
}
__device__ __forceinline__ void ldsm_x4_t(uint32_t* r, uint32_t addr) {
    asm volatile("ldmatrix.sync.aligned.m8n8.x4.trans.shared.b16 {%0,%1,%2,%3}, [%4];"
        : "=r"(r[0]), "=r"(r[1]), "=r"(r[2]), "=r"(r[3]) : "r"(addr));
}
__device__ __forceinline__ void cp_async16(uint32_t dst, const void* src) {
    asm volatile("cp.async.ca.shared.global [%0], [%1], 16;" :: "r"(dst), "l"(src) : "memory");
}
#define CP_COMMIT() asm volatile("cp.async.commit_group;" ::: "memory")
#define CP_WAIT0()  asm volatile("cp.async.wait_group 0;" ::: "memory")

// ---------------- scratch ----------------
__device__ float g_Q[NAC];                 // projected queries (fp32)
__device__ __half g_AOh[NAC], g_AOl[NAC];  // attn output hi/lo planes
__device__ __half g_INh[NAC], g_INl[NAC];  // inputs hi/lo planes
__device__ __half g_W[2][512 * 512];       // wq, wo single fp16 planes
__device__ ull g_maskBits[(size_t)BB * SS * SS / 64];   // 131072 units
__device__ int g_maskKind;
__device__ __half g_KVsp[2][NKV];          // fp16 planes: K, V

// ---------------- mask dtype detect ----------------
__global__ void detect_mask_kernel(const unsigned int* __restrict__ w)
{
    int i32ok = 1, f32ok = 1;
    for (int i = threadIdx.x; i < 16384; i += 256) {
        unsigned int v = w[i];
        if (v > 1u) i32ok = 0;
        if (v != 0u && v != 0x3F800000u) f32ok = 0;
    }
    i32ok = __syncthreads_and(i32ok);
    f32ok = __syncthreads_and(f32ok);
    if (threadIdx.x == 0) g_maskKind = i32ok ? 1 : (f32ok ? 2 : 0);
}

// ---------------- fused prep: bitpack + kv + w + in planes -----------------
// 512 blocks x 256 thr = 131072 threads (tg).
// bitpack: 1 unit per tg (131072 total = full mask).
// kv+in planes: 4 units per thread (u = tg + 131072*j, 524288 total).
// weights: u < 65536.
__global__ __launch_bounds__(256)
void prep_kernel(const void* __restrict__ mask,
                 const float* __restrict__ K, const float* __restrict__ V,
                 const float* __restrict__ wq, const float* __restrict__ wo,
                 const float* __restrict__ A)
{
    const size_t tg = (size_t)blockIdx.x * 256 + threadIdx.x;   // 0..131071
    const int kind = g_maskKind;

    // ---- mask bitpack: unit = tg (full 131072 coverage) ----
    {
        ull bits = 0;
        if (kind == 1) {
            const int4* p = (const int4*)mask + tg * 16;
            #pragma unroll
            for (int w = 0; w < 16; ++w) {
                int4 a = p[w];
                bits |= ((ull)(a.x != 0)) << (4 * w) | ((ull)(a.y != 0)) << (4 * w + 1) |
                        ((ull)(a.z != 0)) << (4 * w + 2) | ((ull)(a.w != 0)) << (4 * w + 3);
            }
        } else if (kind == 2) {
            const float4* p = (const float4*)mask + tg * 16;
            #pragma unroll
            for (int w = 0; w < 16; ++w) {
                float4 a = p[w];
                bits |= ((ull)(a.x != 0.f)) << (4 * w) | ((ull)(a.y != 0.f)) << (4 * w + 1) |
                        ((ull)(a.z != 0.f)) << (4 * w + 2) | ((ull)(a.w != 0.f)) << (4 * w + 3);
            }
        } else {
            const ull* p = (const ull*)mask + tg * 8;
            #pragma unroll
            for (int w = 0; w < 8; ++w) {
                ull v = p[w];
                #pragma unroll
                for (int b8 = 0; b8 < 8; ++b8)
                    bits |= ((ull)(((v >> (8 * b8)) & 0xffull) != 0)) << (8 * w + b8);
            }
        }
        g_maskBits[tg] = bits;
    }

    // ---- K/V + input planes (4 units/thread) ----
    #pragma unroll
    for (int j = 0; j < 4; ++j) {
        size_t u = tg + (size_t)131072 * j;
        {
            float4 v = ((const float4*)K)[u];
            ((uint2*)g_KVsp[0])[u] = make_uint2(packh2(v.x, v.y), packh2(v.z, v.w));
        }
        {
            float4 v = ((const float4*)V)[u];
            ((uint2*)g_KVsp[1])[u] = make_uint2(packh2(v.x, v.y), packh2(v.z, v.w));
        }
        {
            float4 v = ((const float4*)A)[u];
            __half2 h01 = __floats2half2_rn(v.x, v.y);
            __half2 h23 = __floats2half2_rn(v.z, v.w);
            ((uint2*)g_INh)[u] = make_uint2(h2bits(h01), h2bits(h23));
            ((uint2*)g_INl)[u] = make_uint2(
                packh2(v.x - __low2float(h01), v.y - __high2float(h01)),
                packh2(v.z - __low2float(h23), v.w - __high2float(h23)));
        }
    }

    // ---- weight planes (65536 units) ----
    if (tg < 65536) {
        {
            float4 v = ((const float4*)wq)[tg];
            ((uint2*)g_W[0])[tg] = make_uint2(packh2(v.x, v.y), packh2(v.z, v.w));
        }
        {
            float4 v = ((const float4*)wo)[tg];
            ((uint2*)g_W[1])[tg] = make_uint2(packh2(v.x, v.y), packh2(v.z, v.w));
        }
    }
}

// ---------------- fp16 HMMA GEMM, BK=64, cp.async double-buffered ----------
#define GLA 72
#define GLB 72
#define GA_PL (128 * GLA)                 // 9216 elems per A plane
#define GB_OFF (2 * GA_PL)                // 18432
#define GBUF (GB_OFF + 64 * GLB)          // 23040 elems
#define GBUFB (GBUF * 2)                  // 46080 bytes per buffer

__global__ __launch_bounds__(128, 2)
void gemm_fp16_kernel(const __half* __restrict__ Ah, const __half* __restrict__ Al,
                      const __half* __restrict__ W, float* __restrict__ C)
{
    extern __shared__ __align__(16) __half gdyn[];

    const int tid = threadIdx.x;
    const int warp = tid >> 5, lane = tid & 31;
    const int g = lane >> 3, lrow = lane & 7;
    const int mbase = blockIdx.x * 128, nbase = blockIdx.y * 64;

    float Ca[2][8][4];
    #pragma unroll
    for (int i = 0; i < 2; ++i)
        #pragma unroll
        for (int j = 0; j < 8; ++j)
            #pragma unroll
            for (int r = 0; r < 4; ++r) Ca[i][j][r] = 0.f;

    const uint32_t uS = smem_to_u32(gdyn);
    const int arow = warp * 32 + (g & 1) * 8 + lrow;
    const int acol = (g >> 1) * 8;
    const uint32_t bOff = (uint32_t)(((g & 1) * 8 + lrow) * GLB + (g >> 1) * 8) * 2;

    auto stage = [&](int kk, int sel) {
        uint32_t dbase = uS + sel * GBUFB;
        #pragma unroll
        for (int j = 0; j < 16; ++j) {
            int idx = tid + 128 * j;
            int plane = idx >> 10, rem = idx & 1023;
            int row = rem >> 3, seg = rem & 7;
            const __half* src = (plane ? Al : Ah) + (size_t)(mbase + row) * 512 + kk + seg * 8;
            uint32_t dst = dbase + (uint32_t)(plane * GA_PL + row * GLA + seg * 8) * 2;
            cp_async16(dst, src);
        }
        #pragma unroll
        for (int j = 0; j < 4; ++j) {
            int idx = tid + 128 * j;
            int row = idx >> 3, seg = idx & 7;
            const __half* src = W + (size_t)(kk + row) * 512 + nbase + seg * 8;
            uint32_t dst = dbase + (uint32_t)(GB_OFF + row * GLB + seg * 8) * 2;
            cp_async16(dst, src);
        }
        CP_COMMIT();
    };

    stage(0, 0);

    #pragma unroll 1
    for (int c = 0; c < 8; ++c) {
        CP_WAIT0();
        __syncthreads();
        if (c + 1 < 8) stage((c + 1) * 64, (c + 1) & 1);

        const uint32_t ubase = uS + (c & 1) * GBUFB;
        uint32_t Af[2][2][4][4];   // [plane][i][kb]
        #pragma unroll
        for (int p = 0; p < 2; ++p)
            #pragma unroll
            for (int i = 0; i < 2; ++i)
                #pragma unroll
                for (int kb = 0; kb < 4; ++kb)
                    ldsm_x4(Af[p][i][kb], ubase +
                        (uint32_t)(p * GA_PL + (arow + i * 16) * GLA + acol + kb * 16) * 2);

        #pragma unroll
        for (int np = 0; np < 4; ++np) {
            #pragma unroll
            for (int kb = 0; kb < 4; ++kb) {
                uint32_t Bk[4];
                uint32_t off = (uint32_t)(GB_OFF * 2) + (uint32_t)(kb * 16 * GLB + np * 16) * 2;
                ldsm_x4_t(Bk, ubase + off + bOff);
                #pragma unroll
                for (int i = 0; i < 2; ++i) mma_f16(Ca[i][2 * np], Af[0][i][kb], Bk[0], Bk[1]);
                #pragma unroll
                for (int i = 0; i < 2; ++i) mma_f16(Ca[i][2 * np + 1], Af[0][i][kb], Bk[2], Bk[3]);
                #pragma unroll
                for (int i = 0; i < 2; ++i) mma_f16(Ca[i][2 * np], Af[1][i][kb], Bk[0], Bk[1]);
                #pragma unroll
                for (int i = 0; i < 2; ++i) mma_f16(Ca[i][2 * np + 1], Af[1][i][kb], Bk[2], Bk[3]);
            }
        }
    }

    #pragma unroll
    for (int i = 0; i < 2; ++i) {
        int r0 = mbase + warp * 32 + i * 16 + (lane >> 2);
        float* c0 = C + (size_t)r0 * 512 + nbase;
        float* c1 = c0 + (size_t)8 * 512;
        #pragma unroll
        for (int nb = 0; nb < 8; ++nb) {
            int d = nb * 8 + (lane & 3) * 2;
            *(float2*)(c0 + d) = make_float2(Ca[i][nb][0], Ca[i][nb][1]);
            *(float2*)(c1 + d) = make_float2(Ca[i][nb][2], Ca[i][nb][3]);
        }
    }
}

// ---------------- HMMA flash attention, all-single-term fp16 (unchanged) ---
#define LST 72
#define TS (64 * LST)
#define PLB (TS * 2)
#define BUFB (2 * PLB)

__global__ __launch_bounds__(128, 2)
void attn_mma_kernel(const ull* __restrict__ mbits, const float* __restrict__ Q)
{
    extern __shared__ __align__(16) __half dyn[];

    const int b = blockIdx.z, h = blockIdx.y;
    const int qbase = blockIdx.x * 128;
    const int tid = threadIdx.x;
    const int warp = tid >> 5, lane = tid & 31;
    const int g = lane >> 3, lrow = lane & 7;

    {
        const float4* qr = (const float4*)(Q + (size_t)(b * SS + qbase + tid) * EE + h * DD);
        uint32_t* dh = (uint32_t*)(dyn + (tid >= 64 ? TS : 0) + (tid & 63) * LST);
        #pragma unroll
        for (int i = 0; i < 16; ++i) {
            float4 v = qr[i];
            dh[2 * i] = packh2(v.x * 0.125f, v.y * 0.125f);
            dh[2 * i + 1] = packh2(v.z * 0.125f, v.w * 0.125f);
        }
    }
    __syncthreads();

    uint32_t Qh[2][4][4];
    {
        const __half* bh = (warp < 2) ? dyn : dyn + TS;
        const int rowbase = (warp & 1) * 32;
        const int arow = rowbase + (g & 1) * 8 + lrow;
        const int acol = (g >> 1) * 8;
        #pragma unroll
        for (int i = 0; i < 2; ++i)
            #pragma unroll
            for (int kb = 0; kb < 4; ++kb)
                ldsm_x4(Qh[i][kb], smem_to_u32(bh + (arow + i * 16) * LST + acol + kb * 16));
    }
    __syncthreads();

    float Oa[2][8][4];
    #pragma unroll
    for (int i = 0; i < 2; ++i)
        #pragma unroll
        for (int j = 0; j < 8; ++j)
            #pragma unroll
            for (int r = 0; r < 4; ++r) Oa[i][j][r] = 0.f;
    float lsum[4] = {0.f, 0.f, 0.f, 0.f};

    const uint32_t uB = smem_to_u32(dyn);
    const uint32_t kOff = (uint32_t)(((g >> 1) * 8 + lrow) * LST + (g & 1) * 8) * 2;
    const uint32_t vOff = (uint32_t)(((g & 1) * 8 + lrow) * LST + (g >> 1) * 8) * 2;
    const ull* mrow = mbits + (size_t)(b * SS + qbase + warp * 32) * (SS / 64);

    auto stage = [&](int kt, int sel) {
        uint32_t dbase = uB + sel * BUFB;
        #pragma unroll
        for (int j = 0; j < 8; ++j) {
            int idx = tid + 128 * j;
            int plane = idx >> 9;
            int rem = idx & 511;
            int row = rem >> 3, seg = rem & 7;
            const __half* src = g_KVsp[plane] +
                ((size_t)(b * SS + kt + row) * HH + h) * DD + seg * 8;
            uint32_t dst = dbase + (uint32_t)(plane * TS + row * LST + seg * 8) * 2;
            cp_async16(dst, src);
        }
        CP_COMMIT();
    };

    stage(0, 0);

    #pragma unroll 1
    for (int t = 0; t < SS / 64; ++t) {
        CP_WAIT0();
        __syncthreads();
        if (t + 1 < SS / 64) stage((t + 1) * 64, (t + 1) & 1);

        const uint32_t ubase = uB + (t & 1) * BUFB;
        const uint32_t uK = ubase, uV = ubase + PLB;

        float S[2][8][4];
        #pragma unroll
        for (int i = 0; i < 2; ++i)
            #pragma unroll
            for (int j = 0; j < 8; ++j)
                #pragma unroll
                for (int r = 0; r < 4; ++r) S[i][j][r] = 0.f;

        #pragma unroll
        for (int np = 0; np < 4; ++np) {
            #pragma unroll
            for (int kb = 0; kb < 4; ++kb) {
                uint32_t Bk[4];
                uint32_t off = (uint32_t)(np * 16 * LST + kb * 16) * 2;
                ldsm_x4(Bk, uK + off + kOff);
                #pragma unroll
                for (int i = 0; i < 2; ++i) mma_f16(S[i][2 * np], Qh[i][kb], Bk[0], Bk[1]);
                #pragma unroll
                for (int i = 0; i < 2; ++i) mma_f16(S[i][2 * np + 1], Qh[i][kb], Bk[2], Bk[3]);
            }
        }

        uint32_t Ph[2][4][4];
        #pragma unroll
        for (int i = 0; i < 2; ++i) {
            ull mw0 = mrow[(size_t)(i * 16 + (lane >> 2)) * (SS / 64) + t];
            ull mw1 = mrow[(size_t)(i * 16 + 8 + (lane >> 2)) * (SS / 64) + t];
            #pragma unroll
            for (int nb = 0; nb < 8; ++nb) {
                int p0 = nb * 8 + (lane & 3) * 2;
                float e0 = ((mw0 >> p0) & 1ull) ? 0.f : __expf(S[i][nb][0]);
                float e1 = ((mw0 >> (p0 + 1)) & 1ull) ? 0.f : __expf(S[i][nb][1]);
                float e2 = ((mw1 >> p0) & 1ull) ? 0.f : __expf(S[i][nb][2]);
                float e3 = ((mw1 >> (p0 + 1)) & 1ull) ? 0.f : __expf(S[i][nb][3]);
                lsum[i * 2] += e0 + e1;
                lsum[i * 2 + 1] += e2 + e3;
                int kb = nb >> 1, sub = (nb & 1) * 2;
                Ph[i][kb][sub] = packh2(e0, e1);
                Ph[i][kb][sub + 1] = packh2(e2, e3);
            }
        }

        #pragma unroll
        for (int dp = 0; dp < 4; ++dp) {
            #pragma unroll
            for (int kb = 0; kb < 4; ++kb) {
                uint32_t Bv[4];
                uint32_t off = (uint32_t)(kb * 16 * LST + dp * 16) * 2;
                ldsm_x4_t(Bv, uV + off + vOff);
                #pragma unroll
                for (int i = 0; i < 2; ++i) mma_f16(Oa[i][2 * dp], Ph[i][kb], Bv[0], Bv[1]);
                #pragma unroll
                for (int i = 0; i < 2; ++i) mma_f16(Oa[i][2 * dp + 1], Ph[i][kb], Bv[2], Bv[3]);
            }
        }
    }

    #pragma unroll
    for (int i = 0; i < 4; ++i) {
        lsum[i] += __shfl_xor_sync(0xffffffffu, lsum[i], 1);
        lsum[i] += __shfl_xor_sync(0xffffffffu, lsum[i], 2);
    }
    #pragma unroll
    for (int i = 0; i < 2; ++i) {
        float inv0 = 1.f / lsum[i * 2];
        float inv1 = 1.f / lsum[i * 2 + 1];
        int r0 = qbase + warp * 32 + i * 16 + (lane >> 2);
        size_t base0 = (size_t)(b * SS + r0) * EE + h * DD;
        size_t base1 = base0 + (size_t)8 * EE;
        #pragma unroll
        for (int nb = 0; nb < 8; ++nb) {
            int d = nb * 8 + (lane & 3) * 2;
            float v0 = Oa[i][nb][0] * inv0, v1 = Oa[i][nb][1] * inv0;
            float v2 = Oa[i][nb][2] * inv1, v3 = Oa[i][nb][3] * inv1;
            __half2 h01 = __floats2half2_rn(v0, v1);
            __half2 h23 = __floats2half2_rn(v2, v3);
            *(uint32_t*)(g_AOh + base0 + d) = h2bits(h01);
            *(uint32_t*)(g_AOl + base0 + d) =
                packh2(v0 - __low2float(h01), v1 - __high2float(h01));
            *(uint32_t*)(g_AOh + base1 + d) = h2bits(h23);
            *(uint32_t*)(g_AOl + base1 + d) =
                packh2(v2 - __low2float(h23), v3 - __high2float(h23));
        }
    }
}

// ---------------- launch ----------------
extern "C" void kernel_launch(void* const* d_in, const int* in_sizes, int n_in,
                              void* d_out, int out_size)
{
    const float* inputs = (const float*)d_in[0];
    const float* keys = (const float*)d_in[1];
    const float* values = (const float*)d_in[2];
    const float* wq = (const float*)d_in[3];
    const float* wo = (const float*)d_in[4];
    const void* mask_raw = d_in[5];
    float* out = (float*)d_out;

    float* qbuf; ull* mbits;
    __half *inh, *inl, *aoh, *aol, *w0, *w1;
    cudaGetSymbolAddress((void**)&qbuf, g_Q);
    cudaGetSymbolAddress((void**)&mbits, g_maskBits);
    cudaGetSymbolAddress((void**)&inh, g_INh);
    cudaGetSymbolAddress((void**)&inl, g_INl);
    cudaGetSymbolAddress((void**)&aoh, g_AOh);
    cudaGetSymbolAddress((void**)&aol, g_AOl);
    cudaGetSymbolAddress((void**)&w0, g_W);
    w1 = w0 + 512 * 512;

    static int attr_set = 0;
    if (!attr_set) {
        cudaFuncSetAttribute(attn_mma_kernel,
                             cudaFuncAttributeMaxDynamicSharedMemorySize, 2 * BUFB);
        cudaFuncSetAttribute(gemm_fp16_kernel,
                             cudaFuncAttributeMaxDynamicSharedMemorySize, 2 * GBUFB);
        attr_set = 1;
    }

    detect_mask_kernel<<<1, 256>>>((const unsigned int*)mask_raw);
    prep_kernel<<<512, 256>>>(mask_raw, keys, values, wq, wo, inputs);

    dim3 ggrid(32, 8);
    gemm_fp16_kernel<<<ggrid, 128, 2 * GBUFB>>>(inh, inl, w0, qbuf);
    attn_mma_kernel<<<dim3(SS / 128, HH, BB), 128, 2 * BUFB>>>(mbits, qbuf);
    gemm_fp16_kernel<<<ggrid, 128, 2 * GBUFB>>>(aoh, aol, w1, out);
}